// round 10
// baseline (speedup 1.0000x reference)
#include <cuda_runtime.h>
#include <cuda_bf16.h>
#include <math.h>
#include <stdint.h>

typedef unsigned int u32;

// Problem constants
#define B_ 2
#define Q_ 75
#define N_ 5
#define T_ 196
#define C_ 384
#define D_ 384
#define SCALE (1.0f / 14.0f)

// Tiling
#define TPB 256
#define DT 32
#define NSLAB 12
#define HSLAB 6          // slabs per CTA (work split in halves)
#define KP1 13           // GEMM1 k16 panels (t: 196->208)
#define KP2 24           // GEMM2 k16 panels (c: 384)
#define NG2 25           // GEMM2 G-groups (t: 196->200)
#define NT2 200          // GEMM2 N (t padded to 200)

// packed panel sizes (u32 words)
#define A1_PANEL 512     // [pl2][T2][lane32][reg4]
#define B1_PANEL 6144    // [G48][lane32][bh0,bh1,bl0,bl1]
#define B2_PANEL 3200    // [G25][lane32][bh0,bh1,bl0,bl1]

__device__ u32 g_A1[150 * NSLAB * KP1 * A1_PANEL];  // ~45.7 MB
__device__ u32 g_B1[10 * KP1 * B1_PANEL];           // ~3.2 MB
__device__ u32 g_B2[150 * KP2 * B2_PANEL];          // ~46 MB
__device__ float g_pn[1500 * NT2];
__device__ float g_pq[1500 * NT2];
__device__ float g_nfs[10 * T_];
__device__ float g_top1[B_ * Q_ * N_];

// smem layout (u32 offsets)
#define U_A2   0                        // A2 frags [p24][pl2][T2][lane32][r4] = 12288
#define U_B    12288                    // B staging dbuf: 2*6144
#define U_A1   (U_B + 2 * B1_PANEL)     // 24576: A1 dbuf 2*512
#define U_PN   (U_A1 + 2 * A1_PANEL)    // 25600: [200]
#define U_PQ   (U_PN + NT2)             // 25800
#define U_RINV (U_PQ + NT2)             // 26000: [32]
#define U_PMAX (U_RINV + 32)            // 26032: [32][8]
#define U_PSUM (U_PMAX + 256)           // 26288
#define U_TOT  (U_PSUM + 256)           // 26544 u32 = 106176 B (2 CTAs = 212.4 KB)

__device__ __forceinline__ u32 bpack_hi(float x0, float x1) {
    __nv_bfloat162 h;
    h.x = __float2bfloat16(x0);
    h.y = __float2bfloat16(x1);
    return *(u32*)&h;
}
__device__ __forceinline__ u32 bpack_lo(float x0, float x1) {
    __nv_bfloat16 h0 = __float2bfloat16(x0);
    __nv_bfloat16 h1 = __float2bfloat16(x1);
    __nv_bfloat162 l;
    l.x = __float2bfloat16(x0 - __bfloat162float(h0));
    l.y = __float2bfloat16(x1 - __bfloat162float(h1));
    return *(u32*)&l;
}
__device__ __forceinline__ void bsplit2(float x0, float x1, u32& hw, u32& lw) {
    __nv_bfloat16 h0 = __float2bfloat16(x0);
    __nv_bfloat16 h1 = __float2bfloat16(x1);
    __nv_bfloat162 hh; hh.x = h0; hh.y = h1;
    hw = *(u32*)&hh;
    __nv_bfloat162 ll;
    ll.x = __float2bfloat16(x0 - __bfloat162float(h0));
    ll.y = __float2bfloat16(x1 - __bfloat162float(h1));
    lw = *(u32*)&ll;
}

__device__ __forceinline__ void mma16(float* c, const u32* a, u32 b0, u32 b1) {
    asm volatile(
        "mma.sync.aligned.m16n8k16.row.col.f32.bf16.bf16.f32 "
        "{%0,%1,%2,%3},{%4,%5,%6,%7},{%8,%9},{%0,%1,%2,%3};"
        : "+f"(c[0]), "+f"(c[1]), "+f"(c[2]), "+f"(c[3])
        : "r"(a[0]), "r"(a[1]), "r"(a[2]), "r"(a[3]), "r"(b0), "r"(b1));
}

__device__ __forceinline__ void cp16(u32 daddr, const void* src) {
    asm volatile("cp.async.cg.shared.global [%0], [%1], 16;" :: "r"(daddr), "l"(src));
}
#define CP_COMMIT() asm volatile("cp.async.commit_group;" ::: "memory")
#define CP_WAIT0()  asm volatile("cp.async.wait_group 0;" ::: "memory")

// ==================== pack kernels ====================

// A1[m=d][k=t] = SCALE * Fq[t][d], fragment dump per (bq, slab, panel)
__global__ void pack_a1(const float* __restrict__ fq) {
    __shared__ float tile[16][33];
    int bid = blockIdx.x;                 // (bq*NSLAB+s)*KP1 + p
    int p  = bid % KP1;
    int s  = (bid / KP1) % NSLAB;
    int bq = bid / (KP1 * NSLAB);
    const float* Fq = fq + (size_t)bq * T_ * C_;
    int d0 = s * DT;
    for (int idx = threadIdx.x; idx < 16 * DT; idx += 256) {
        int k = idx >> 5, d = idx & 31;
        int t = p * 16 + k;
        tile[k][d] = (t < T_) ? SCALE * Fq[(size_t)t * C_ + d0 + d] : 0.f;
    }
    __syncthreads();
    u32* dst = g_A1 + (size_t)bid * A1_PANEL;
    for (int idx = threadIdx.x; idx < A1_PANEL; idx += 256) {
        int pl  = idx >> 8;
        int rem = idx & 255;
        int T   = rem >> 7;
        int lane = (rem >> 2) & 31;
        int reg  = idx & 3;
        int grr = lane >> 2, gcc = lane & 3;
        int dl = T * 16 + grr + ((reg & 1) ? 8 : 0);
        int kl = 2 * gcc + ((reg & 2) ? 8 : 0);
        float x0 = tile[kl][dl], x1 = tile[kl + 1][dl];
        dst[idx] = pl ? bpack_lo(x0, x1) : bpack_hi(x0, x1);
    }
}

// B1[k=t][n=c] = Fs[t][c], layout [G48][lane32][j4] j:0,1=hi 2,3=lo
__global__ void pack_b1(const float* __restrict__ fs) {
    __shared__ float tile[16][385];
    int bid = blockIdx.x;                 // bn*KP1 + p
    int p  = bid % KP1;
    int bn = bid / KP1;
    const float* Fs = fs + (size_t)bn * T_ * C_;
    for (int idx = threadIdx.x; idx < 16 * C_; idx += 256) {
        int k = idx / C_, c = idx % C_;
        int t = p * 16 + k;
        tile[k][c] = (t < T_) ? Fs[(size_t)t * C_ + c] : 0.f;
    }
    __syncthreads();
    u32* dst = g_B1 + (size_t)bid * B1_PANEL;
    for (int idx = threadIdx.x; idx < B1_PANEL; idx += 256) {
        int G    = idx >> 7;
        int lane = (idx >> 2) & 31;
        int j    = idx & 3;
        int pl   = j >> 1;
        int reg  = j & 1;
        int grr = lane >> 2, gcc = lane & 3;
        int n  = G * 8 + grr;
        int kl = 2 * gcc + 8 * reg;
        float x0 = tile[kl][n], x1 = tile[kl + 1][n];
        dst[idx] = pl ? bpack_lo(x0, x1) : bpack_hi(x0, x1);
    }
}

// B2[k=c][n=t] = Fq[t][c], layout [G25][lane32][j4]
__global__ void pack_b2(const float* __restrict__ fq) {
    __shared__ float tile[T_][17];
    int bid = blockIdx.x;                 // bq*KP2 + p
    int p  = bid % KP2;
    int bq = bid / KP2;
    const float* Fq = fq + (size_t)bq * T_ * C_;
    for (int idx = threadIdx.x; idx < T_ * 16; idx += 256) {
        int t = idx >> 4, c = idx & 15;
        tile[t][c] = Fq[(size_t)t * C_ + p * 16 + c];
    }
    __syncthreads();
    u32* dst = g_B2 + (size_t)bid * B2_PANEL;
    for (int idx = threadIdx.x; idx < B2_PANEL; idx += 256) {
        int G    = idx >> 7;
        int lane = (idx >> 2) & 31;
        int j    = idx & 3;
        int pl   = j >> 1;
        int reg  = j & 1;
        int grr = lane >> 2, gcc = lane & 3;
        int t  = G * 8 + grr;
        int kl = 2 * gcc + 8 * reg;
        float x0 = 0.f, x1 = 0.f;
        if (t < T_) { x0 = tile[t][kl]; x1 = tile[t][kl + 1]; }
        dst[idx] = pl ? bpack_lo(x0, x1) : bpack_hi(x0, x1);
    }
}

// Fs token L2 norms: one block per bn
__global__ void fsnorm_kernel(const float* __restrict__ fs) {
    int bn = blockIdx.x;
    int wid = threadIdx.x >> 5, lane = threadIdx.x & 31;
    const float* Fs = fs + (size_t)bn * T_ * C_;
    for (int r = wid; r < T_; r += 8) {
        float s = 0.f;
        #pragma unroll
        for (int u = 0; u < 12; u++) {
            float v = Fs[(size_t)r * C_ + lane + 32 * u];
            s += v * v;
        }
        #pragma unroll
        for (int o = 16; o > 0; o >>= 1) s += __shfl_xor_sync(0xffffffffu, s, o);
        if (lane == 0) g_nfs[bn * T_ + r] = sqrtf(s);
    }
}

// ==================== main kernel ====================

__global__ __launch_bounds__(TPB, 2)
void episodic_main(const float* __restrict__ fs_g) {
    extern __shared__ u32 smu[];
    float* smf = (float*)smu;
    const u32 smbase = (u32)__cvta_generic_to_shared(smu);

    const int cid = blockIdx.x;      // 0..1499
    const int bx = cid >> 1;         // episode index 0..749
    const int half = cid & 1;        // slab half
    const int nn = bx % N_;
    const int bq = bx / N_;          // b*75+q
    const int bb = bq / Q_;
    const int bn = bb * N_ + nn;
    const float* __restrict__ Fs = fs_g + (size_t)bn * T_ * C_;

    const int tid = threadIdx.x;
    const int wid = tid >> 5, lane = tid & 31;
    const int gr = lane >> 2, gc = lane & 3;
    // GEMM2 N split over 8 warps: wid0 -> 4 groups, others 3 (total 25)
    const int ng2 = (wid == 0) ? 4 : 3;
    const int g2base = (wid == 0) ? 0 : 4 + (wid - 1) * 3;

    for (int i = tid; i < NT2; i += TPB) { smf[U_PN + i] = 0.f; smf[U_PQ + i] = 0.f; }
    __syncthreads();

    const u32* gB1 = g_B1 + (size_t)bn * KP1 * B1_PANEL;
    const u32* gB2 = g_B2 + (size_t)bq * KP2 * B2_PANEL;

    for (int s = 0; s < HSLAB; s++) {
        const int slab = half * HSLAB + s;
        const int d0 = slab * DT;
        const u32* gA1 = g_A1 + (size_t)(bq * NSLAB + slab) * KP1 * A1_PANEL;

        // ---------------- GEMM1: S[32][384] ----------------
        float acc1[2][6][4];
        #pragma unroll
        for (int mt = 0; mt < 2; mt++)
            #pragma unroll
            for (int nt = 0; nt < 6; nt++)
                #pragma unroll
                for (int e = 0; e < 4; e++) acc1[mt][nt][e] = 0.f;

        {
            const float4* srcB = (const float4*)(gB1);
            u32 dstB = smbase + (U_B) * 4;
            #pragma unroll
            for (int j = 0; j < 6; j++) cp16(dstB + (tid + j * TPB) * 16, srcB + tid + j * TPB);
            if (tid < 128) {
                const float4* srcA = (const float4*)(gA1);
                cp16(smbase + (U_A1) * 4 + tid * 16, srcA + tid);
            }
            CP_COMMIT();
        }
        for (int p = 0; p < KP1; p++) {
            const int buf = p & 1;
            CP_WAIT0();
            __syncthreads();
            if (p + 1 < KP1) {
                const float4* srcB = (const float4*)(gB1 + (size_t)(p + 1) * B1_PANEL);
                u32 dstB = smbase + (U_B + (buf ^ 1) * B1_PANEL) * 4;
                #pragma unroll
                for (int j = 0; j < 6; j++) cp16(dstB + (tid + j * TPB) * 16, srcB + tid + j * TPB);
                if (tid < 128) {
                    const float4* srcA = (const float4*)(gA1 + (size_t)(p + 1) * A1_PANEL);
                    cp16(smbase + (U_A1 + (buf ^ 1) * A1_PANEL) * 4 + tid * 16, srcA + tid);
                }
                CP_COMMIT();
            }
            const u32* bA = smu + U_A1 + buf * A1_PANEL;
            const u32* bB = smu + U_B + buf * B1_PANEL;
            u32 ah[2][4], al[2][4];
            #pragma unroll
            for (int mt = 0; mt < 2; mt++) {
                uint4 h = *(const uint4*)&bA[((0 * 2 + mt) * 32 + lane) * 4];
                uint4 l = *(const uint4*)&bA[((1 * 2 + mt) * 32 + lane) * 4];
                ah[mt][0] = h.x; ah[mt][1] = h.y; ah[mt][2] = h.z; ah[mt][3] = h.w;
                al[mt][0] = l.x; al[mt][1] = l.y; al[mt][2] = l.z; al[mt][3] = l.w;
            }
            #pragma unroll
            for (int nt = 0; nt < 6; nt++) {
                int G = wid * 6 + nt;
                uint4 b4 = *(const uint4*)&bB[(G * 32 + lane) * 4];
                #pragma unroll
                for (int mt = 0; mt < 2; mt++) {
                    mma16(acc1[mt][nt], ah[mt], b4.x, b4.y);
                    mma16(acc1[mt][nt], ah[mt], b4.z, b4.w);
                    mma16(acc1[mt][nt], al[mt], b4.x, b4.y);
                }
            }
        }

        // ---------------- softmax (row max/sum across 8 warps) ----------------
        #pragma unroll
        for (int mt = 0; mt < 2; mt++)
            #pragma unroll
            for (int h = 0; h < 2; h++) {
                float mx = -INFINITY;
                #pragma unroll
                for (int nt = 0; nt < 6; nt++)
                    mx = fmaxf(mx, fmaxf(acc1[mt][nt][2 * h], acc1[mt][nt][2 * h + 1]));
                mx = fmaxf(mx, __shfl_xor_sync(0xffffffffu, mx, 1));
                mx = fmaxf(mx, __shfl_xor_sync(0xffffffffu, mx, 2));
                int row = mt * 16 + gr + 8 * h;
                if (gc == 0) smf[U_PMAX + row * 8 + wid] = mx;
            }
        __syncthreads();
        #pragma unroll
        for (int mt = 0; mt < 2; mt++)
            #pragma unroll
            for (int h = 0; h < 2; h++) {
                int row = mt * 16 + gr + 8 * h;
                float gmax = -INFINITY;
                #pragma unroll
                for (int w = 0; w < 8; w++)
                    gmax = fmaxf(gmax, smf[U_PMAX + row * 8 + w]);
                float s2 = 0.f;
                #pragma unroll
                for (int nt = 0; nt < 6; nt++) {
                    float v0 = __expf(acc1[mt][nt][2 * h] - gmax);
                    float v1 = __expf(acc1[mt][nt][2 * h + 1] - gmax);
                    acc1[mt][nt][2 * h] = v0;
                    acc1[mt][nt][2 * h + 1] = v1;
                    s2 += v0 + v1;
                }
                s2 += __shfl_xor_sync(0xffffffffu, s2, 1);
                s2 += __shfl_xor_sync(0xffffffffu, s2, 2);
                if (gc == 0) smf[U_PSUM + row * 8 + wid] = s2;
            }
        __syncthreads();
        if (wid == 0 && gc == 0) {
            #pragma unroll
            for (int mt = 0; mt < 2; mt++)
                #pragma unroll
                for (int h = 0; h < 2; h++) {
                    int row = mt * 16 + gr + 8 * h;
                    float tot = 0.f;
                    #pragma unroll
                    for (int w = 0; w < 8; w++) tot += smf[U_PSUM + row * 8 + w];
                    smf[U_RINV + row] = 1.0f / tot;
                }
        }

        // pack Pexp into GEMM2 A-fragment layout (hi/lo, STS.128)
        #pragma unroll
        for (int mt = 0; mt < 2; mt++) {
            #pragma unroll
            for (int np = 0; np < 3; np++) {
                int G0 = wid * 6 + 2 * np;
                int p  = G0 >> 1;
                u32 vh[4], vl[4];
                bsplit2(acc1[mt][2 * np][0], acc1[mt][2 * np][1], vh[0], vl[0]);
                bsplit2(acc1[mt][2 * np][2], acc1[mt][2 * np][3], vh[1], vl[1]);
                bsplit2(acc1[mt][2 * np + 1][0], acc1[mt][2 * np + 1][1], vh[2], vl[2]);
                bsplit2(acc1[mt][2 * np + 1][2], acc1[mt][2 * np + 1][3], vh[3], vl[3]);
                *(uint4*)&smu[U_A2 + (((p * 2 + 0) * 2 + mt) * 32 + lane) * 4] =
                    make_uint4(vh[0], vh[1], vh[2], vh[3]);
                *(uint4*)&smu[U_A2 + (((p * 2 + 1) * 2 + mt) * 32 + lane) * 4] =
                    make_uint4(vl[0], vl[1], vl[2], vl[3]);
            }
        }
        __syncthreads();

        // ---------------- GEMM2: fq_new^T[32][200] ----------------
        float acc2[2][4][4];
        #pragma unroll
        for (int mt = 0; mt < 2; mt++)
            #pragma unroll
            for (int nt = 0; nt < 4; nt++)
                #pragma unroll
                for (int e = 0; e < 4; e++) acc2[mt][nt][e] = 0.f;

        {
            const float4* srcB = (const float4*)(gB2);
            u32 dstB = smbase + (U_B) * 4;
            #pragma unroll
            for (int j = 0; j < 4; j++) {
                int i = tid + j * TPB;
                if (i < 800) cp16(dstB + i * 16, srcB + i);
            }
            CP_COMMIT();
        }
        for (int p = 0; p < KP2; p++) {
            const int buf = p & 1;
            CP_WAIT0();
            __syncthreads();
            if (p + 1 < KP2) {
                const float4* srcB = (const float4*)(gB2 + (size_t)(p + 1) * B2_PANEL);
                u32 dstB = smbase + (U_B + (buf ^ 1) * B1_PANEL) * 4;
                #pragma unroll
                for (int j = 0; j < 4; j++) {
                    int i = tid + j * TPB;
                    if (i < 800) cp16(dstB + i * 16, srcB + i);
                }
                CP_COMMIT();
            }
            const u32* bB = smu + U_B + buf * B1_PANEL;
            u32 ah[2][4], al[2][4];
            #pragma unroll
            for (int mt = 0; mt < 2; mt++) {
                uint4 h = *(const uint4*)&smu[U_A2 + (((p * 2 + 0) * 2 + mt) * 32 + lane) * 4];
                uint4 l = *(const uint4*)&smu[U_A2 + (((p * 2 + 1) * 2 + mt) * 32 + lane) * 4];
                ah[mt][0] = h.x; ah[mt][1] = h.y; ah[mt][2] = h.z; ah[mt][3] = h.w;
                al[mt][0] = l.x; al[mt][1] = l.y; al[mt][2] = l.z; al[mt][3] = l.w;
            }
            for (int nt = 0; nt < ng2; nt++) {
                int G = g2base + nt;
                uint4 b4 = *(const uint4*)&bB[(G * 32 + lane) * 4];
                #pragma unroll
                for (int mt = 0; mt < 2; mt++) {
                    mma16(acc2[mt][nt], ah[mt], b4.x, b4.y);
                    mma16(acc2[mt][nt], ah[mt], b4.z, b4.w);
                    mma16(acc2[mt][nt], al[mt], b4.x, b4.y);
                }
            }
        }
        __syncthreads();

        // ---------------- epilogue: rinv, num/norm2 partials ----------------
        for (int nt = 0; nt < ng2; nt++) {
            int G = g2base + nt;
            int ta = G * 8 + 2 * gc;
            int tb = ta + 1;
            float pn_a = 0.f, pq_a = 0.f, pn_b = 0.f, pq_b = 0.f;
            #pragma unroll
            for (int mt = 0; mt < 2; mt++) {
                int rb1 = mt * 16 + gr;
                int rb2 = rb1 + 8;
                float r1 = smf[U_RINV + rb1];
                float r2 = smf[U_RINV + rb2];
                float v0 = acc2[mt][nt][0] * r1;
                float v1 = acc2[mt][nt][1] * r1;
                float v2 = acc2[mt][nt][2] * r2;
                float v3 = acc2[mt][nt][3] * r2;
                int gd1 = d0 + rb1, gd2 = d0 + rb2;
                float fa1 = 0.f, fa2 = 0.f, fb1 = 0.f, fb2 = 0.f;
                if (ta < T_) { fa1 = Fs[(size_t)ta * C_ + gd1]; fa2 = Fs[(size_t)ta * C_ + gd2]; }
                if (tb < T_) { fb1 = Fs[(size_t)tb * C_ + gd1]; fb2 = Fs[(size_t)tb * C_ + gd2]; }
                pn_a += v0 * fa1 + v2 * fa2;
                pq_a += v0 * v0 + v2 * v2;
                pn_b += v1 * fb1 + v3 * fb2;
                pq_b += v1 * v1 + v3 * v3;
            }
            #pragma unroll
            for (int o = 4; o <= 16; o <<= 1) {
                pn_a += __shfl_xor_sync(0xffffffffu, pn_a, o);
                pq_a += __shfl_xor_sync(0xffffffffu, pq_a, o);
                pn_b += __shfl_xor_sync(0xffffffffu, pn_b, o);
                pq_b += __shfl_xor_sync(0xffffffffu, pq_b, o);
            }
            if (lane < 4) {
                smf[U_PN + ta] += pn_a;
                smf[U_PQ + ta] += pq_a;
                smf[U_PN + tb] += pn_b;
                smf[U_PQ + tb] += pq_b;
            }
        }
        __syncthreads();
    }  // slab loop

    // write partials to gmem
    if (tid < NT2) {
        g_pn[(size_t)cid * NT2 + tid] = smf[U_PN + tid];
        g_pq[(size_t)cid * NT2 + tid] = smf[U_PQ + tid];
    }
}

// ==================== reduce / epilogue kernels ====================

// one warp per episode: combine halves, cosine, top1 max
__global__ void top1_kernel() {
    int w = (blockIdx.x * blockDim.x + threadIdx.x) >> 5;
    int lane = threadIdx.x & 31;
    if (w >= B_ * Q_ * N_) return;
    int nn = w % N_;
    int bq = w / N_;
    int bb = bq / Q_;
    int bn = bb * N_ + nn;
    float local = -INFINITY;
    for (int t = lane; t < T_; t += 32) {
        float num = g_pn[(size_t)(2 * w) * NT2 + t] + g_pn[(size_t)(2 * w + 1) * NT2 + t];
        float nrm = g_pq[(size_t)(2 * w) * NT2 + t] + g_pq[(size_t)(2 * w + 1) * NT2 + t];
        float denom = fmaxf(sqrtf(nrm) * g_nfs[bn * T_ + t], 1e-8f);
        local = fmaxf(local, num / denom);
    }
    #pragma unroll
    for (int o = 16; o > 0; o >>= 1)
        local = fmaxf(local, __shfl_xor_sync(0xffffffffu, local, o));
    if (lane == 0) g_top1[w] = local;
}

__global__ void finalize_logits_kernel(float* __restrict__ out) {
    int i = blockIdx.x * blockDim.x + threadIdx.x;
    if (i < B_ * Q_) {
        float s = 0.f;
        #pragma unroll
        for (int n = 0; n < N_; n++) s += g_top1[i * N_ + n];
        out[i] = s * (1.0f / N_);
    }
}

__global__ void cls_kernel(const float* __restrict__ xq,
                           const float* __restrict__ xs,
                           float* __restrict__ out) {
    int w = (blockIdx.x * blockDim.x + threadIdx.x) >> 5;
    int lid = threadIdx.x & 31;
    if (w >= B_ * Q_ * N_) return;
    int nn = w % N_;
    int qq = (w / N_) % Q_;
    int bb = w / (N_ * Q_);
    const float* q = xq + (size_t)(bb * Q_ + qq) * D_;
    const float* s = xs + (size_t)(bb * N_ + nn) * D_;
    float dot = 0.f, nq = 0.f, ns = 0.f;
    #pragma unroll
    for (int u = 0; u < D_ / 32; u++) {
        float a = q[lid + 32 * u];
        float b = s[lid + 32 * u];
        dot += a * b;
        nq += a * a;
        ns += b * b;
    }
    #pragma unroll
    for (int o = 16; o > 0; o >>= 1) {
        dot += __shfl_xor_sync(0xffffffffu, dot, o);
        nq  += __shfl_xor_sync(0xffffffffu, nq, o);
        ns  += __shfl_xor_sync(0xffffffffu, ns, o);
    }
    if (lid == 0) {
        float den = fmaxf(sqrtf(nq), 1e-12f) * fmaxf(sqrtf(ns), 1e-12f);
        out[B_ * Q_ + w] = 10.0f * dot / den;
    }
}

extern "C" void kernel_launch(void* const* d_in, const int* in_sizes, int n_in,
                              void* d_out, int out_size) {
    const float* fq = (const float*)d_in[0];  // (2,75,196,384)
    const float* fs = (const float*)d_in[1];  // (2,5,1,196,384)
    const float* xq = (const float*)d_in[2];  // (2,75,384)
    const float* xs = (const float*)d_in[3];  // (2,5,1,384)
    float* out = (float*)d_out;               // [150 logits][750 cls_logits]

    pack_a1<<<150 * NSLAB * KP1, 256>>>(fq);
    pack_b1<<<10 * KP1, 256>>>(fs);
    pack_b2<<<150 * KP2, 256>>>(fq);
    fsnorm_kernel<<<10, 256>>>(fs);

    const size_t smem_bytes = (size_t)U_TOT * sizeof(u32);
    cudaFuncSetAttribute(episodic_main,
                         cudaFuncAttributeMaxDynamicSharedMemorySize,
                         (int)smem_bytes);
    episodic_main<<<1500, TPB, smem_bytes>>>(fs);

    top1_kernel<<<(B_ * Q_ * N_ * 32 + 255) / 256, 256>>>();
    finalize_logits_kernel<<<1, 256>>>(out);
    cls_kernel<<<(B_ * Q_ * N_ * 32 + 255) / 256, 256>>>(xq, xs, out);
}

// round 11
// speedup vs baseline: 1.0197x; 1.0197x over previous
#include <cuda_runtime.h>
#include <cuda_bf16.h>
#include <math.h>
#include <stdint.h>

typedef unsigned int u32;

#define B_ 2
#define Q_ 75
#define N_ 5
#define T_ 196
#define C_ 384
#define D_ 384
#define SCALE (1.0f / 14.0f)

#define TPB 256
#define DT 32
#define NSLAB 12
#define HSLAB 6
#define KP1 13
#define KP2 24
#define NG2 25
#define NT2 200

#define A1_PANEL 512
#define B1_PANEL 6144
#define B2_PANEL 3200

__device__ u32 g_A1[150 * NSLAB * KP1 * A1_PANEL];
__device__ u32 g_B1[10 * KP1 * B1_PANEL];
__device__ u32 g_B2[150 * KP2 * B2_PANEL];
__device__ float g_pn[1500 * NT2];
__device__ float g_pq[1500 * NT2];
__device__ float g_nfs[10 * T_];
__device__ float g_top1[B_ * Q_ * N_];

#define U_A2   0
#define U_B    12288
#define U_A1   (U_B + 2 * B1_PANEL)
#define U_PN   (U_A1 + 2 * A1_PANEL)
#define U_PQ   (U_PN + NT2)
#define U_RINV (U_PQ + NT2)
#define U_PMAX (U_RINV + 32)
#define U_PSUM (U_PMAX + 256)
#define U_TOT  (U_PSUM + 256)

__device__ __forceinline__ u32 bpack_hi(float x0, float x1) {
    __nv_bfloat162 h; h.x = __float2bfloat16(x0); h.y = __float2bfloat16(x1);
    return *(u32*)&h;
}
__device__ __forceinline__ u32 bpack_lo(float x0, float x1) {
    __nv_bfloat16 h0 = __float2bfloat16(x0);
    __nv_bfloat16 h1 = __float2bfloat16(x1);
    __nv_bfloat162 l;
    l.x = __float2bfloat16(x0 - __bfloat162float(h0));
    l.y = __float2bfloat16(x1 - __bfloat162float(h1));
    return *(u32*)&l;
}
__device__ __forceinline__ void bsplit2(float x0, float x1, u32& hw, u32& lw) {
    __nv_bfloat16 h0 = __float2bfloat16(x0);
    __nv_bfloat16 h1 = __float2bfloat16(x1);
    __nv_bfloat162 hh; hh.x = h0; hh.y = h1;
    hw = *(u32*)&hh;
    __nv_bfloat162 ll;
    ll.x = __float2bfloat16(x0 - __bfloat162float(h0));
    ll.y = __float2bfloat16(x1 - __bfloat162float(h1));
    lw = *(u32*)&ll;
}

__device__ __forceinline__ void mma16(float* c, const u32* a, u32 b0, u32 b1) {
    asm volatile(
        "mma.sync.aligned.m16n8k16.row.col.f32.bf16.bf16.f32 "
        "{%0,%1,%2,%3},{%4,%5,%6,%7},{%8,%9},{%0,%1,%2,%3};"
        : "+f"(c[0]), "+f"(c[1]), "+f"(c[2]), "+f"(c[3])
        : "r"(a[0]), "r"(a[1]), "r"(a[2]), "r"(a[3]), "r"(b0), "r"(b1));
}

__device__ __forceinline__ void cp16(u32 daddr, const void* src) {
    asm volatile("cp.async.cg.shared.global [%0], [%1], 16;" :: "r"(daddr), "l"(src));
}
#define CP_COMMIT() asm volatile("cp.async.commit_group;" ::: "memory")
#define CP_WAIT0()  asm volatile("cp.async.wait_group 0;" ::: "memory")

// ==================== pack kernels (unchanged layouts) ====================

__global__ void pack_a1(const float* __restrict__ fq) {
    __shared__ float tile[16][33];
    int bid = blockIdx.x;
    int p  = bid % KP1;
    int s  = (bid / KP1) % NSLAB;
    int bq = bid / (KP1 * NSLAB);
    const float* Fq = fq + (size_t)bq * T_ * C_;
    int d0 = s * DT;
    for (int idx = threadIdx.x; idx < 16 * DT; idx += 256) {
        int k = idx >> 5, d = idx & 31;
        int t = p * 16 + k;
        tile[k][d] = (t < T_) ? SCALE * Fq[(size_t)t * C_ + d0 + d] : 0.f;
    }
    __syncthreads();
    u32* dst = g_A1 + (size_t)bid * A1_PANEL;
    for (int idx = threadIdx.x; idx < A1_PANEL; idx += 256) {
        int pl  = idx >> 8;
        int rem = idx & 255;
        int T   = rem >> 7;
        int lane = (rem >> 2) & 31;
        int reg  = idx & 3;
        int grr = lane >> 2, gcc = lane & 3;
        int dl = T * 16 + grr + ((reg & 1) ? 8 : 0);
        int kl = 2 * gcc + ((reg & 2) ? 8 : 0);
        float x0 = tile[kl][dl], x1 = tile[kl + 1][dl];
        dst[idx] = pl ? bpack_lo(x0, x1) : bpack_hi(x0, x1);
    }
}

__global__ void pack_b1(const float* __restrict__ fs) {
    __shared__ float tile[16][385];
    int bid = blockIdx.x;
    int p  = bid % KP1;
    int bn = bid / KP1;
    const float* Fs = fs + (size_t)bn * T_ * C_;
    for (int idx = threadIdx.x; idx < 16 * C_; idx += 256) {
        int k = idx / C_, c = idx % C_;
        int t = p * 16 + k;
        tile[k][c] = (t < T_) ? Fs[(size_t)t * C_ + c] : 0.f;
    }
    __syncthreads();
    u32* dst = g_B1 + (size_t)bid * B1_PANEL;
    for (int idx = threadIdx.x; idx < B1_PANEL; idx += 256) {
        int G    = idx >> 7;
        int lane = (idx >> 2) & 31;
        int j    = idx & 3;
        int pl   = j >> 1;
        int reg  = j & 1;
        int grr = lane >> 2, gcc = lane & 3;
        int n  = G * 8 + grr;
        int kl = 2 * gcc + 8 * reg;
        float x0 = tile[kl][n], x1 = tile[kl + 1][n];
        dst[idx] = pl ? bpack_lo(x0, x1) : bpack_hi(x0, x1);
    }
}

__global__ void pack_b2(const float* __restrict__ fq) {
    __shared__ float tile[T_][17];
    int bid = blockIdx.x;
    int p  = bid % KP2;
    int bq = bid / KP2;
    const float* Fq = fq + (size_t)bq * T_ * C_;
    for (int idx = threadIdx.x; idx < T_ * 16; idx += 256) {
        int t = idx >> 4, c = idx & 15;
        tile[t][c] = Fq[(size_t)t * C_ + p * 16 + c];
    }
    __syncthreads();
    u32* dst = g_B2 + (size_t)bid * B2_PANEL;
    for (int idx = threadIdx.x; idx < B2_PANEL; idx += 256) {
        int G    = idx >> 7;
        int lane = (idx >> 2) & 31;
        int j    = idx & 3;
        int pl   = j >> 1;
        int reg  = j & 1;
        int grr = lane >> 2, gcc = lane & 3;
        int t  = G * 8 + grr;
        int kl = 2 * gcc + 8 * reg;
        float x0 = 0.f, x1 = 0.f;
        if (t < T_) { x0 = tile[t][kl]; x1 = tile[t][kl + 1]; }
        dst[idx] = pl ? bpack_lo(x0, x1) : bpack_hi(x0, x1);
    }
}

// Fs token norms: 70 blocks (10 bn x 7 row-chunks of 28)
__global__ void fsnorm_kernel(const float* __restrict__ fs) {
    int bn = blockIdx.x / 7;
    int base = (blockIdx.x % 7) * 28;
    int wid = threadIdx.x >> 5, lane = threadIdx.x & 31;
    const float* Fs = fs + (size_t)bn * T_ * C_;
    for (int r = base + wid; r < base + 28 && r < T_; r += 8) {
        float s = 0.f;
        #pragma unroll
        for (int u = 0; u < 12; u++) {
            float v = Fs[(size_t)r * C_ + lane + 32 * u];
            s += v * v;
        }
        #pragma unroll
        for (int o = 16; o > 0; o >>= 1) s += __shfl_xor_sync(0xffffffffu, s, o);
        if (lane == 0) g_nfs[bn * T_ + r] = sqrtf(s);
    }
}

// ==================== main kernel ====================

__global__ __launch_bounds__(TPB, 2)
void episodic_main(const float* __restrict__ fs_g) {
    extern __shared__ u32 smu[];
    float* smf = (float*)smu;
    const u32 smbase = (u32)__cvta_generic_to_shared(smu);

    const int cid = blockIdx.x;
    const int bx = cid >> 1;
    const int half = cid & 1;
    const int nn = bx % N_;
    const int bq = bx / N_;
    const int bb = bq / Q_;
    const int bn = bb * N_ + nn;
    const float* __restrict__ Fs = fs_g + (size_t)bn * T_ * C_;

    const int tid = threadIdx.x;
    const int wid = tid >> 5, lane = tid & 31;
    const int gr = lane >> 2, gc = lane & 3;
    const int ng2 = (wid == 0) ? 4 : 3;
    const int g2base = (wid == 0) ? 0 : 4 + (wid - 1) * 3;

    for (int i = tid; i < NT2; i += TPB) { smf[U_PN + i] = 0.f; smf[U_PQ + i] = 0.f; }
    __syncthreads();

    const u32* gB1 = g_B1 + (size_t)bn * KP1 * B1_PANEL;
    const u32* gB2 = g_B2 + (size_t)bq * KP2 * B2_PANEL;

    for (int s = 0; s < HSLAB; s++) {
        const int slab = half * HSLAB + s;
        const int d0 = slab * DT;
        const u32* gA1 = g_A1 + (size_t)(bq * NSLAB + slab) * KP1 * A1_PANEL;

        // ---------------- GEMM1 ----------------
        float acc1[2][6][4];
        #pragma unroll
        for (int mt = 0; mt < 2; mt++)
            #pragma unroll
            for (int nt = 0; nt < 6; nt++)
                #pragma unroll
                for (int e = 0; e < 4; e++) acc1[mt][nt][e] = 0.f;

        {
            const float4* srcB = (const float4*)(gB1);
            u32 dstB = smbase + (U_B) * 4;
            #pragma unroll
            for (int j = 0; j < 6; j++) cp16(dstB + (tid + j * TPB) * 16, srcB + tid + j * TPB);
            if (tid < 128) cp16(smbase + (U_A1) * 4 + tid * 16, ((const float4*)gA1) + tid);
            CP_COMMIT();
        }
        for (int p = 0; p < KP1; p++) {
            const int buf = p & 1;
            CP_WAIT0();
            __syncthreads();
            if (p + 1 < KP1) {
                const float4* srcB = (const float4*)(gB1 + (size_t)(p + 1) * B1_PANEL);
                u32 dstB = smbase + (U_B + (buf ^ 1) * B1_PANEL) * 4;
                #pragma unroll
                for (int j = 0; j < 6; j++) cp16(dstB + (tid + j * TPB) * 16, srcB + tid + j * TPB);
                if (tid < 128)
                    cp16(smbase + (U_A1 + (buf ^ 1) * A1_PANEL) * 4 + tid * 16,
                         ((const float4*)(gA1 + (size_t)(p + 1) * A1_PANEL)) + tid);
                CP_COMMIT();
            }
            const u32* bA = smu + U_A1 + buf * A1_PANEL;
            const u32* bB = smu + U_B + buf * B1_PANEL;
            u32 ah[2][4], al[2][4];
            #pragma unroll
            for (int mt = 0; mt < 2; mt++) {
                uint4 h = *(const uint4*)&bA[((0 * 2 + mt) * 32 + lane) * 4];
                uint4 l = *(const uint4*)&bA[((1 * 2 + mt) * 32 + lane) * 4];
                ah[mt][0] = h.x; ah[mt][1] = h.y; ah[mt][2] = h.z; ah[mt][3] = h.w;
                al[mt][0] = l.x; al[mt][1] = l.y; al[mt][2] = l.z; al[mt][3] = l.w;
            }
            // nt pairs, term-major: same-accumulator mmas are 4 apart
            #pragma unroll
            for (int np = 0; np < 3; np++) {
                int G0 = wid * 6 + 2 * np;
                uint4 b0 = *(const uint4*)&bB[(G0 * 32 + lane) * 4];
                uint4 b1 = *(const uint4*)&bB[((G0 + 1) * 32 + lane) * 4];
                #pragma unroll
                for (int mt = 0; mt < 2; mt++) mma16(acc1[mt][2 * np],     ah[mt], b0.x, b0.y);
                #pragma unroll
                for (int mt = 0; mt < 2; mt++) mma16(acc1[mt][2 * np + 1], ah[mt], b1.x, b1.y);
                #pragma unroll
                for (int mt = 0; mt < 2; mt++) mma16(acc1[mt][2 * np],     ah[mt], b0.z, b0.w);
                #pragma unroll
                for (int mt = 0; mt < 2; mt++) mma16(acc1[mt][2 * np + 1], ah[mt], b1.z, b1.w);
                #pragma unroll
                for (int mt = 0; mt < 2; mt++) mma16(acc1[mt][2 * np],     al[mt], b0.x, b0.y);
                #pragma unroll
                for (int mt = 0; mt < 2; mt++) mma16(acc1[mt][2 * np + 1], al[mt], b1.x, b1.y);
            }
        }

        // ---------------- softmax ----------------
        #pragma unroll
        for (int mt = 0; mt < 2; mt++)
            #pragma unroll
            for (int h = 0; h < 2; h++) {
                float mx = -INFINITY;
                #pragma unroll
                for (int nt = 0; nt < 6; nt++)
                    mx = fmaxf(mx, fmaxf(acc1[mt][nt][2 * h], acc1[mt][nt][2 * h + 1]));
                mx = fmaxf(mx, __shfl_xor_sync(0xffffffffu, mx, 1));
                mx = fmaxf(mx, __shfl_xor_sync(0xffffffffu, mx, 2));
                int row = mt * 16 + gr + 8 * h;
                if (gc == 0) smf[U_PMAX + row * 8 + wid] = mx;
            }
        __syncthreads();
        #pragma unroll
        for (int mt = 0; mt < 2; mt++)
            #pragma unroll
            for (int h = 0; h < 2; h++) {
                int row = mt * 16 + gr + 8 * h;
                float gmax = -INFINITY;
                #pragma unroll
                for (int w = 0; w < 8; w++)
                    gmax = fmaxf(gmax, smf[U_PMAX + row * 8 + w]);
                float s2 = 0.f;
                #pragma unroll
                for (int nt = 0; nt < 6; nt++) {
                    float v0 = __expf(acc1[mt][nt][2 * h] - gmax);
                    float v1 = __expf(acc1[mt][nt][2 * h + 1] - gmax);
                    acc1[mt][nt][2 * h] = v0;
                    acc1[mt][nt][2 * h + 1] = v1;
                    s2 += v0 + v1;
                }
                s2 += __shfl_xor_sync(0xffffffffu, s2, 1);
                s2 += __shfl_xor_sync(0xffffffffu, s2, 2);
                if (gc == 0) smf[U_PSUM + row * 8 + wid] = s2;
            }
        __syncthreads();
        if (wid == 0 && gc == 0) {
            #pragma unroll
            for (int mt = 0; mt < 2; mt++)
                #pragma unroll
                for (int h = 0; h < 2; h++) {
                    int row = mt * 16 + gr + 8 * h;
                    float tot = 0.f;
                    #pragma unroll
                    for (int w = 0; w < 8; w++) tot += smf[U_PSUM + row * 8 + w];
                    smf[U_RINV + row] = 1.0f / tot;
                }
        }

        // pack Pexp into GEMM2 A-fragment layout
        #pragma unroll
        for (int mt = 0; mt < 2; mt++) {
            #pragma unroll
            for (int np = 0; np < 3; np++) {
                int G0 = wid * 6 + 2 * np;
                int p  = G0 >> 1;
                u32 vh[4], vl[4];
                bsplit2(acc1[mt][2 * np][0], acc1[mt][2 * np][1], vh[0], vl[0]);
                bsplit2(acc1[mt][2 * np][2], acc1[mt][2 * np][3], vh[1], vl[1]);
                bsplit2(acc1[mt][2 * np + 1][0], acc1[mt][2 * np + 1][1], vh[2], vl[2]);
                bsplit2(acc1[mt][2 * np + 1][2], acc1[mt][2 * np + 1][3], vh[3], vl[3]);
                *(uint4*)&smu[U_A2 + (((p * 2 + 0) * 2 + mt) * 32 + lane) * 4] =
                    make_uint4(vh[0], vh[1], vh[2], vh[3]);
                *(uint4*)&smu[U_A2 + (((p * 2 + 1) * 2 + mt) * 32 + lane) * 4] =
                    make_uint4(vl[0], vl[1], vl[2], vl[3]);
            }
        }
        __syncthreads();

        // ---------------- GEMM2 ----------------
        float acc2[2][4][4];
        #pragma unroll
        for (int mt = 0; mt < 2; mt++)
            #pragma unroll
            for (int nt = 0; nt < 4; nt++)
                #pragma unroll
                for (int e = 0; e < 4; e++) acc2[mt][nt][e] = 0.f;

        {
            const float4* srcB = (const float4*)(gB2);
            u32 dstB = smbase + (U_B) * 4;
            #pragma unroll
            for (int j = 0; j < 4; j++) {
                int i = tid + j * TPB;
                if (i < 800) cp16(dstB + i * 16, srcB + i);
            }
            CP_COMMIT();
        }
        for (int p = 0; p < KP2; p++) {
            const int buf = p & 1;
            CP_WAIT0();
            __syncthreads();
            if (p + 1 < KP2) {
                const float4* srcB = (const float4*)(gB2 + (size_t)(p + 1) * B2_PANEL);
                u32 dstB = smbase + (U_B + (buf ^ 1) * B1_PANEL) * 4;
                #pragma unroll
                for (int j = 0; j < 4; j++) {
                    int i = tid + j * TPB;
                    if (i < 800) cp16(dstB + i * 16, srcB + i);
                }
                CP_COMMIT();
            }
            const u32* bB = smu + U_B + buf * B1_PANEL;
            u32 ah[2][4], al[2][4];
            #pragma unroll
            for (int mt = 0; mt < 2; mt++) {
                uint4 h = *(const uint4*)&smu[U_A2 + (((p * 2 + 0) * 2 + mt) * 32 + lane) * 4];
                uint4 l = *(const uint4*)&smu[U_A2 + (((p * 2 + 1) * 2 + mt) * 32 + lane) * 4];
                ah[mt][0] = h.x; ah[mt][1] = h.y; ah[mt][2] = h.z; ah[mt][3] = h.w;
                al[mt][0] = l.x; al[mt][1] = l.y; al[mt][2] = l.z; al[mt][3] = l.w;
            }
            // term-major per nt: same-acc distance 2
            for (int nt = 0; nt < ng2; nt++) {
                int G = g2base + nt;
                uint4 b4 = *(const uint4*)&bB[(G * 32 + lane) * 4];
                #pragma unroll
                for (int mt = 0; mt < 2; mt++) mma16(acc2[mt][nt], ah[mt], b4.x, b4.y);
                #pragma unroll
                for (int mt = 0; mt < 2; mt++) mma16(acc2[mt][nt], ah[mt], b4.z, b4.w);
                #pragma unroll
                for (int mt = 0; mt < 2; mt++) mma16(acc2[mt][nt], al[mt], b4.x, b4.y);
            }
        }
        __syncthreads();

        // ---------------- epilogue ----------------
        for (int nt = 0; nt < ng2; nt++) {
            int G = g2base + nt;
            int ta = G * 8 + 2 * gc;
            int tb = ta + 1;
            float pn_a = 0.f, pq_a = 0.f, pn_b = 0.f, pq_b = 0.f;
            #pragma unroll
            for (int mt = 0; mt < 2; mt++) {
                int rb1 = mt * 16 + gr;
                int rb2 = rb1 + 8;
                float r1 = smf[U_RINV + rb1];
                float r2 = smf[U_RINV + rb2];
                float v0 = acc2[mt][nt][0] * r1;
                float v1 = acc2[mt][nt][1] * r1;
                float v2 = acc2[mt][nt][2] * r2;
                float v3 = acc2[mt][nt][3] * r2;
                int gd1 = d0 + rb1, gd2 = d0 + rb2;
                float fa1 = 0.f, fa2 = 0.f, fb1 = 0.f, fb2 = 0.f;
                if (ta < T_) { fa1 = Fs[(size_t)ta * C_ + gd1]; fa2 = Fs[(size_t)ta * C_ + gd2]; }
                if (tb < T_) { fb1 = Fs[(size_t)tb * C_ + gd1]; fb2 = Fs[(size_t)tb * C_ + gd2]; }
                pn_a += v0 * fa1 + v2 * fa2;
                pq_a += v0 * v0 + v2 * v2;
                pn_b += v1 * fb1 + v3 * fb2;
                pq_b += v1 * v1 + v3 * v3;
            }
            #pragma unroll
            for (int o = 4; o <= 16; o <<= 1) {
                pn_a += __shfl_xor_sync(0xffffffffu, pn_a, o);
                pq_a += __shfl_xor_sync(0xffffffffu, pq_a, o);
                pn_b += __shfl_xor_sync(0xffffffffu, pn_b, o);
                pq_b += __shfl_xor_sync(0xffffffffu, pq_b, o);
            }
            if (lane < 4) {
                smf[U_PN + ta] += pn_a;
                smf[U_PQ + ta] += pq_a;
                smf[U_PN + tb] += pn_b;
                smf[U_PQ + tb] += pq_b;
            }
        }
        __syncthreads();
    }

    if (tid < NT2) {
        g_pn[(size_t)cid * NT2 + tid] = smf[U_PN + tid];
        g_pq[(size_t)cid * NT2 + tid] = smf[U_PQ + tid];
    }
}

// ==================== reduce / epilogue kernels ====================

__global__ void top1_kernel() {
    int w = (blockIdx.x * blockDim.x + threadIdx.x) >> 5;
    int lane = threadIdx.x & 31;
    if (w >= B_ * Q_ * N_) return;
    int nn = w % N_;
    int bq = w / N_;
    int bb = bq / Q_;
    int bn = bb * N_ + nn;
    float local = -INFINITY;
    for (int t = lane; t < T_; t += 32) {
        float num = g_pn[(size_t)(2 * w) * NT2 + t] + g_pn[(size_t)(2 * w + 1) * NT2 + t];
        float nrm = g_pq[(size_t)(2 * w) * NT2 + t] + g_pq[(size_t)(2 * w + 1) * NT2 + t];
        float denom = fmaxf(sqrtf(nrm) * g_nfs[bn * T_ + t], 1e-8f);
        local = fmaxf(local, num / denom);
    }
    #pragma unroll
    for (int o = 16; o > 0; o >>= 1)
        local = fmaxf(local, __shfl_xor_sync(0xffffffffu, local, o));
    if (lane == 0) g_top1[w] = local;
}

__global__ void finalize_logits_kernel(float* __restrict__ out) {
    int i = blockIdx.x * blockDim.x + threadIdx.x;
    if (i < B_ * Q_) {
        float s = 0.f;
        #pragma unroll
        for (int n = 0; n < N_; n++) s += g_top1[i * N_ + n];
        out[i] = s * (1.0f / N_);
    }
}

__global__ void cls_kernel(const float* __restrict__ xq,
                           const float* __restrict__ xs,
                           float* __restrict__ out) {
    int w = (blockIdx.x * blockDim.x + threadIdx.x) >> 5;
    int lid = threadIdx.x & 31;
    if (w >= B_ * Q_ * N_) return;
    int nn = w % N_;
    int qq = (w / N_) % Q_;
    int bb = w / (N_ * Q_);
    const float* q = xq + (size_t)(bb * Q_ + qq) * D_;
    const float* s = xs + (size_t)(bb * N_ + nn) * D_;
    float dot = 0.f, nq = 0.f, ns = 0.f;
    #pragma unroll
    for (int u = 0; u < D_ / 32; u++) {
        float a = q[lid + 32 * u];
        float b = s[lid + 32 * u];
        dot += a * b;
        nq += a * a;
        ns += b * b;
    }
    #pragma unroll
    for (int o = 16; o > 0; o >>= 1) {
        dot += __shfl_xor_sync(0xffffffffu, dot, o);
        nq  += __shfl_xor_sync(0xffffffffu, nq, o);
        ns  += __shfl_xor_sync(0xffffffffu, ns, o);
    }
    if (lid == 0) {
        float den = fmaxf(sqrtf(nq), 1e-12f) * fmaxf(sqrtf(ns), 1e-12f);
        out[B_ * Q_ + w] = 10.0f * dot / den;
    }
}

extern "C" void kernel_launch(void* const* d_in, const int* in_sizes, int n_in,
                              void* d_out, int out_size) {
    const float* fq = (const float*)d_in[0];
    const float* fs = (const float*)d_in[1];
    const float* xq = (const float*)d_in[2];
    const float* xs = (const float*)d_in[3];
    float* out = (float*)d_out;

    pack_a1<<<150 * NSLAB * KP1, 256>>>(fq);
    pack_b1<<<10 * KP1, 256>>>(fs);
    pack_b2<<<150 * KP2, 256>>>(fq);
    fsnorm_kernel<<<70, 256>>>(fs);

    const size_t smem_bytes = (size_t)U_TOT * sizeof(u32);
    cudaFuncSetAttribute(episodic_main,
                         cudaFuncAttributeMaxDynamicSharedMemorySize,
                         (int)smem_bytes);
    episodic_main<<<1500, TPB, smem_bytes>>>(fs);

    top1_kernel<<<(B_ * Q_ * N_ * 32 + 255) / 256, 256>>>();
    finalize_logits_kernel<<<1, 256>>>(out);
    cls_kernel<<<(B_ * Q_ * N_ * 32 + 255) / 256, 256>>>(xq, xs, out);
}

// round 12
// speedup vs baseline: 1.2576x; 1.2334x over previous
#include <cuda_runtime.h>
#include <cuda_fp16.h>
#include <math.h>
#include <stdint.h>

typedef unsigned int u32;

#define B_ 2
#define Q_ 75
#define N_ 5
#define T_ 196
#define C_ 384
#define D_ 384
#define SCALE (1.0f / 14.0f)

#define TPB 256
#define DT 32
#define NSLAB 12
#define HSLAB 6
#define KP1 13
#define KP2 24
#define NT2 200

#define A1_PANEL 256     // [T2][lane32][reg4] fp16x2 hi only
#define B1_PANEL 6144    // [G48][lane32][bh0,bh1,bl0,bl1]
#define B2_PANEL 3200    // [G25][lane32][bh0,bh1,bl0,bl1]

__device__ u32 g_A1[150 * NSLAB * KP1 * A1_PANEL];
__device__ u32 g_B1[10 * KP1 * B1_PANEL];
__device__ u32 g_B2[150 * KP2 * B2_PANEL];
__device__ float g_pn[1500 * NT2];
__device__ float g_pq[1500 * NT2];
__device__ float g_nfs[10 * T_];
__device__ float g_top1[B_ * Q_ * N_];

// smem layout (u32 offsets)
#define U_A2   0                         // [p24][mt2][lane32][r4] = 6144
#define U_B    6144                      // dbuf 2*6144
#define U_A1   (U_B + 2 * B1_PANEL)      // 18432: dbuf 2*256
#define U_PN   (U_A1 + 2 * A1_PANEL)     // 18944
#define U_PQ   (U_PN + NT2)
#define U_RINV (U_PQ + NT2)
#define U_PMAX (U_RINV + 32)
#define U_PSUM (U_PMAX + 256)
#define U_TOT  (U_PSUM + 256)            // 19888 u32 = 79552 B

__device__ __forceinline__ u32 hpack(float x0, float x1) {
    __half2 h; h.x = __float2half_rn(x0); h.y = __float2half_rn(x1);
    return *(u32*)&h;
}
__device__ __forceinline__ u32 hpack_lo(float x0, float x1) {
    __half h0 = __float2half_rn(x0);
    __half h1 = __float2half_rn(x1);
    __half2 l;
    l.x = __float2half_rn(x0 - __half2float(h0));
    l.y = __float2half_rn(x1 - __half2float(h1));
    return *(u32*)&l;
}

__device__ __forceinline__ void mma16(float* c, const u32* a, u32 b0, u32 b1) {
    asm volatile(
        "mma.sync.aligned.m16n8k16.row.col.f32.f16.f16.f32 "
        "{%0,%1,%2,%3},{%4,%5,%6,%7},{%8,%9},{%0,%1,%2,%3};"
        : "+f"(c[0]), "+f"(c[1]), "+f"(c[2]), "+f"(c[3])
        : "r"(a[0]), "r"(a[1]), "r"(a[2]), "r"(a[3]), "r"(b0), "r"(b1));
}

__device__ __forceinline__ void cp16(u32 daddr, const void* src) {
    asm volatile("cp.async.cg.shared.global [%0], [%1], 16;" :: "r"(daddr), "l"(src));
}
#define CP_COMMIT() asm volatile("cp.async.commit_group;" ::: "memory")
#define CP_WAIT0()  asm volatile("cp.async.wait_group 0;" ::: "memory")

// ==================== pack kernels ====================

// A1[m=d][k=t] = SCALE * Fq[t][d], fp16 hi only, frag layout [T2][lane32][reg4]
__global__ void pack_a1(const float* __restrict__ fq) {
    __shared__ float tile[16][33];
    int bid = blockIdx.x;
    int p  = bid % KP1;
    int s  = (bid / KP1) % NSLAB;
    int bq = bid / (KP1 * NSLAB);
    const float* Fq = fq + (size_t)bq * T_ * C_;
    int d0 = s * DT;
    for (int idx = threadIdx.x; idx < 16 * DT; idx += 256) {
        int k = idx >> 5, d = idx & 31;
        int t = p * 16 + k;
        tile[k][d] = (t < T_) ? SCALE * Fq[(size_t)t * C_ + d0 + d] : 0.f;
    }
    __syncthreads();
    u32* dst = g_A1 + (size_t)bid * A1_PANEL;
    if (threadIdx.x < A1_PANEL) {
        int idx = threadIdx.x;
        int T   = (idx >> 7) & 1;
        int lane = (idx >> 2) & 31;
        int reg  = idx & 3;
        int grr = lane >> 2, gcc = lane & 3;
        int dl = T * 16 + grr + ((reg & 1) ? 8 : 0);
        int kl = 2 * gcc + ((reg & 2) ? 8 : 0);
        dst[idx] = hpack(tile[kl][dl], tile[kl + 1][dl]);
    }
}

// B1[k=t][n=c] = Fs[t][c], fp16 hi/lo, layout [G48][lane32][bh0,bh1,bl0,bl1]
__global__ void pack_b1(const float* __restrict__ fs) {
    __shared__ float tile[16][385];
    int bid = blockIdx.x;
    int p  = bid % KP1;
    int bn = bid / KP1;
    const float* Fs = fs + (size_t)bn * T_ * C_;
    for (int idx = threadIdx.x; idx < 16 * C_; idx += 256) {
        int k = idx / C_, c = idx % C_;
        int t = p * 16 + k;
        tile[k][c] = (t < T_) ? Fs[(size_t)t * C_ + c] : 0.f;
    }
    __syncthreads();
    u32* dst = g_B1 + (size_t)bid * B1_PANEL;
    for (int idx = threadIdx.x; idx < B1_PANEL; idx += 256) {
        int G    = idx >> 7;
        int lane = (idx >> 2) & 31;
        int j    = idx & 3;
        int pl   = j >> 1;
        int reg  = j & 1;
        int grr = lane >> 2, gcc = lane & 3;
        int n  = G * 8 + grr;
        int kl = 2 * gcc + 8 * reg;
        float x0 = tile[kl][n], x1 = tile[kl + 1][n];
        dst[idx] = pl ? hpack_lo(x0, x1) : hpack(x0, x1);
    }
}

// B2[k=c][n=t] = Fq[t][c], fp16 hi/lo, layout [G25][lane32][j4]
__global__ void pack_b2(const float* __restrict__ fq) {
    __shared__ float tile[T_][17];
    int bid = blockIdx.x;
    int p  = bid % KP2;
    int bq = bid / KP2;
    const float* Fq = fq + (size_t)bq * T_ * C_;
    for (int idx = threadIdx.x; idx < T_ * 16; idx += 256) {
        int t = idx >> 4, c = idx & 15;
        tile[t][c] = Fq[(size_t)t * C_ + p * 16 + c];
    }
    __syncthreads();
    u32* dst = g_B2 + (size_t)bid * B2_PANEL;
    for (int idx = threadIdx.x; idx < B2_PANEL; idx += 256) {
        int G    = idx >> 7;
        int lane = (idx >> 2) & 31;
        int j    = idx & 3;
        int pl   = j >> 1;
        int reg  = j & 1;
        int grr = lane >> 2, gcc = lane & 3;
        int t  = G * 8 + grr;
        int kl = 2 * gcc + 8 * reg;
        float x0 = 0.f, x1 = 0.f;
        if (t < T_) { x0 = tile[t][kl]; x1 = tile[t][kl + 1]; }
        dst[idx] = pl ? hpack_lo(x0, x1) : hpack(x0, x1);
    }
}

__global__ void fsnorm_kernel(const float* __restrict__ fs) {
    int bn = blockIdx.x / 7;
    int base = (blockIdx.x % 7) * 28;
    int wid = threadIdx.x >> 5, lane = threadIdx.x & 31;
    const float* Fs = fs + (size_t)bn * T_ * C_;
    for (int r = base + wid; r < base + 28 && r < T_; r += 8) {
        float s = 0.f;
        #pragma unroll
        for (int u = 0; u < 12; u++) {
            float v = Fs[(size_t)r * C_ + lane + 32 * u];
            s += v * v;
        }
        #pragma unroll
        for (int o = 16; o > 0; o >>= 1) s += __shfl_xor_sync(0xffffffffu, s, o);
        if (lane == 0) g_nfs[bn * T_ + r] = sqrtf(s);
    }
}

// ==================== main kernel ====================

__global__ __launch_bounds__(TPB, 2)
void episodic_main(const float* __restrict__ fs_g) {
    extern __shared__ u32 smu[];
    float* smf = (float*)smu;
    const u32 smbase = (u32)__cvta_generic_to_shared(smu);

    const int cid = blockIdx.x;
    const int bx = cid >> 1;
    const int half = cid & 1;
    const int nn = bx % N_;
    const int bq = bx / N_;
    const int bb = bq / Q_;
    const int bn = bb * N_ + nn;
    const float* __restrict__ Fs = fs_g + (size_t)bn * T_ * C_;

    const int tid = threadIdx.x;
    const int wid = tid >> 5, lane = tid & 31;
    const int gr = lane >> 2, gc = lane & 3;
    const int ng2 = (wid == 0) ? 4 : 3;
    const int g2base = (wid == 0) ? 0 : 4 + (wid - 1) * 3;

    for (int i = tid; i < NT2; i += TPB) { smf[U_PN + i] = 0.f; smf[U_PQ + i] = 0.f; }
    __syncthreads();

    const u32* gB1 = g_B1 + (size_t)bn * KP1 * B1_PANEL;
    const u32* gB2 = g_B2 + (size_t)bq * KP2 * B2_PANEL;

    for (int s = 0; s < HSLAB; s++) {
        const int slab = half * HSLAB + s;
        const int d0 = slab * DT;
        const u32* gA1 = g_A1 + (size_t)(bq * NSLAB + slab) * KP1 * A1_PANEL;

        // ---------------- GEMM1 ----------------
        float acc1[2][6][4];
        #pragma unroll
        for (int mt = 0; mt < 2; mt++)
            #pragma unroll
            for (int nt = 0; nt < 6; nt++)
                #pragma unroll
                for (int e = 0; e < 4; e++) acc1[mt][nt][e] = 0.f;

        {
            const float4* srcB = (const float4*)(gB1);
            u32 dstB = smbase + (U_B) * 4;
            #pragma unroll
            for (int j = 0; j < 6; j++) cp16(dstB + (tid + j * TPB) * 16, srcB + tid + j * TPB);
            if (tid < 64) cp16(smbase + (U_A1) * 4 + tid * 16, ((const float4*)gA1) + tid);
            CP_COMMIT();
        }
        for (int p = 0; p < KP1; p++) {
            const int buf = p & 1;
            CP_WAIT0();
            __syncthreads();
            if (p + 1 < KP1) {
                const float4* srcB = (const float4*)(gB1 + (size_t)(p + 1) * B1_PANEL);
                u32 dstB = smbase + (U_B + (buf ^ 1) * B1_PANEL) * 4;
                #pragma unroll
                for (int j = 0; j < 6; j++) cp16(dstB + (tid + j * TPB) * 16, srcB + tid + j * TPB);
                if (tid < 64)
                    cp16(smbase + (U_A1 + (buf ^ 1) * A1_PANEL) * 4 + tid * 16,
                         ((const float4*)(gA1 + (size_t)(p + 1) * A1_PANEL)) + tid);
                CP_COMMIT();
            }
            const u32* bA = smu + U_A1 + buf * A1_PANEL;
            const u32* bB = smu + U_B + buf * B1_PANEL;
            u32 ah[2][4];
            #pragma unroll
            for (int mt = 0; mt < 2; mt++) {
                uint4 h = *(const uint4*)&bA[(mt * 32 + lane) * 4];
                ah[mt][0] = h.x; ah[mt][1] = h.y; ah[mt][2] = h.z; ah[mt][3] = h.w;
            }
            // 2-term fp16: ah*bh + ah*bl; same-acc distance 4
            #pragma unroll
            for (int np = 0; np < 3; np++) {
                int G0 = wid * 6 + 2 * np;
                uint4 b0 = *(const uint4*)&bB[(G0 * 32 + lane) * 4];
                uint4 b1 = *(const uint4*)&bB[((G0 + 1) * 32 + lane) * 4];
                #pragma unroll
                for (int mt = 0; mt < 2; mt++) mma16(acc1[mt][2 * np],     ah[mt], b0.x, b0.y);
                #pragma unroll
                for (int mt = 0; mt < 2; mt++) mma16(acc1[mt][2 * np + 1], ah[mt], b1.x, b1.y);
                #pragma unroll
                for (int mt = 0; mt < 2; mt++) mma16(acc1[mt][2 * np],     ah[mt], b0.z, b0.w);
                #pragma unroll
                for (int mt = 0; mt < 2; mt++) mma16(acc1[mt][2 * np + 1], ah[mt], b1.z, b1.w);
            }
        }

        // ---------------- softmax ----------------
        #pragma unroll
        for (int mt = 0; mt < 2; mt++)
            #pragma unroll
            for (int h = 0; h < 2; h++) {
                float mx = -INFINITY;
                #pragma unroll
                for (int nt = 0; nt < 6; nt++)
                    mx = fmaxf(mx, fmaxf(acc1[mt][nt][2 * h], acc1[mt][nt][2 * h + 1]));
                mx = fmaxf(mx, __shfl_xor_sync(0xffffffffu, mx, 1));
                mx = fmaxf(mx, __shfl_xor_sync(0xffffffffu, mx, 2));
                int row = mt * 16 + gr + 8 * h;
                if (gc == 0) smf[U_PMAX + row * 8 + wid] = mx;
            }
        __syncthreads();
        #pragma unroll
        for (int mt = 0; mt < 2; mt++)
            #pragma unroll
            for (int h = 0; h < 2; h++) {
                int row = mt * 16 + gr + 8 * h;
                float gmax = -INFINITY;
                #pragma unroll
                for (int w = 0; w < 8; w++)
                    gmax = fmaxf(gmax, smf[U_PMAX + row * 8 + w]);
                float s2 = 0.f;
                #pragma unroll
                for (int nt = 0; nt < 6; nt++) {
                    float v0 = __expf(acc1[mt][nt][2 * h] - gmax);
                    float v1 = __expf(acc1[mt][nt][2 * h + 1] - gmax);
                    acc1[mt][nt][2 * h] = v0;
                    acc1[mt][nt][2 * h + 1] = v1;
                    s2 += v0 + v1;
                }
                s2 += __shfl_xor_sync(0xffffffffu, s2, 1);
                s2 += __shfl_xor_sync(0xffffffffu, s2, 2);
                if (gc == 0) smf[U_PSUM + row * 8 + wid] = s2;
            }
        __syncthreads();
        if (wid == 0 && gc == 0) {
            #pragma unroll
            for (int mt = 0; mt < 2; mt++)
                #pragma unroll
                for (int h = 0; h < 2; h++) {
                    int row = mt * 16 + gr + 8 * h;
                    float tot = 0.f;
                    #pragma unroll
                    for (int w = 0; w < 8; w++) tot += smf[U_PSUM + row * 8 + w];
                    smf[U_RINV + row] = 1.0f / tot;
                }
        }

        // pack Pexp (fp16 hi only) into GEMM2 A-fragment layout
        #pragma unroll
        for (int mt = 0; mt < 2; mt++) {
            #pragma unroll
            for (int np = 0; np < 3; np++) {
                int G0 = wid * 6 + 2 * np;
                int p  = G0 >> 1;
                u32 vh0 = hpack(acc1[mt][2 * np][0], acc1[mt][2 * np][1]);
                u32 vh1 = hpack(acc1[mt][2 * np][2], acc1[mt][2 * np][3]);
                u32 vh2 = hpack(acc1[mt][2 * np + 1][0], acc1[mt][2 * np + 1][1]);
                u32 vh3 = hpack(acc1[mt][2 * np + 1][2], acc1[mt][2 * np + 1][3]);
                *(uint4*)&smu[U_A2 + ((p * 2 + mt) * 32 + lane) * 4] =
                    make_uint4(vh0, vh1, vh2, vh3);
            }
        }
        __syncthreads();

        // ---------------- GEMM2 ----------------
        float acc2[2][4][4];
        #pragma unroll
        for (int mt = 0; mt < 2; mt++)
            #pragma unroll
            for (int nt = 0; nt < 4; nt++)
                #pragma unroll
                for (int e = 0; e < 4; e++) acc2[mt][nt][e] = 0.f;

        {
            const float4* srcB = (const float4*)(gB2);
            u32 dstB = smbase + (U_B) * 4;
            #pragma unroll
            for (int j = 0; j < 4; j++) {
                int i = tid + j * TPB;
                if (i < 800) cp16(dstB + i * 16, srcB + i);
            }
            CP_COMMIT();
        }
        for (int p = 0; p < KP2; p++) {
            const int buf = p & 1;
            CP_WAIT0();
            __syncthreads();
            if (p + 1 < KP2) {
                const float4* srcB = (const float4*)(gB2 + (size_t)(p + 1) * B2_PANEL);
                u32 dstB = smbase + (U_B + (buf ^ 1) * B1_PANEL) * 4;
                #pragma unroll
                for (int j = 0; j < 4; j++) {
                    int i = tid + j * TPB;
                    if (i < 800) cp16(dstB + i * 16, srcB + i);
                }
                CP_COMMIT();
            }
            const u32* bB = smu + U_B + buf * B1_PANEL;
            u32 ah[2][4];
            #pragma unroll
            for (int mt = 0; mt < 2; mt++) {
                uint4 h = *(const uint4*)&smu[U_A2 + ((p * 2 + mt) * 32 + lane) * 4];
                ah[mt][0] = h.x; ah[mt][1] = h.y; ah[mt][2] = h.z; ah[mt][3] = h.w;
            }
            for (int nt = 0; nt < ng2; nt++) {
                int G = g2base + nt;
                uint4 b4 = *(const uint4*)&bB[(G * 32 + lane) * 4];
                #pragma unroll
                for (int mt = 0; mt < 2; mt++) mma16(acc2[mt][nt], ah[mt], b4.x, b4.y);
                #pragma unroll
                for (int mt = 0; mt < 2; mt++) mma16(acc2[mt][nt], ah[mt], b4.z, b4.w);
            }
        }
        __syncthreads();

        // ---------------- epilogue ----------------
        for (int nt = 0; nt < ng2; nt++) {
            int G = g2base + nt;
            int ta = G * 8 + 2 * gc;
            int tb = ta + 1;
            float pn_a = 0.f, pq_a = 0.f, pn_b = 0.f, pq_b = 0.f;
            #pragma unroll
            for (int mt = 0; mt < 2; mt++) {
                int rb1 = mt * 16 + gr;
                int rb2 = rb1 + 8;
                float r1 = smf[U_RINV + rb1];
                float r2 = smf[U_RINV + rb2];
                float v0 = acc2[mt][nt][0] * r1;
                float v1 = acc2[mt][nt][1] * r1;
                float v2 = acc2[mt][nt][2] * r2;
                float v3 = acc2[mt][nt][3] * r2;
                int gd1 = d0 + rb1, gd2 = d0 + rb2;
                float fa1 = 0.f, fa2 = 0.f, fb1 = 0.f, fb2 = 0.f;
                if (ta < T_) { fa1 = Fs[(size_t)ta * C_ + gd1]; fa2 = Fs[(size_t)ta * C_ + gd2]; }
                if (tb < T_) { fb1 = Fs[(size_t)tb * C_ + gd1]; fb2 = Fs[(size_t)tb * C_ + gd2]; }
                pn_a += v0 * fa1 + v2 * fa2;
                pq_a += v0 * v0 + v2 * v2;
                pn_b += v1 * fb1 + v3 * fb2;
                pq_b += v1 * v1 + v3 * v3;
            }
            #pragma unroll
            for (int o = 4; o <= 16; o <<= 1) {
                pn_a += __shfl_xor_sync(0xffffffffu, pn_a, o);
                pq_a += __shfl_xor_sync(0xffffffffu, pq_a, o);
                pn_b += __shfl_xor_sync(0xffffffffu, pn_b, o);
                pq_b += __shfl_xor_sync(0xffffffffu, pq_b, o);
            }
            if (lane < 4) {
                smf[U_PN + ta] += pn_a;
                smf[U_PQ + ta] += pq_a;
                smf[U_PN + tb] += pn_b;
                smf[U_PQ + tb] += pq_b;
            }
        }
        __syncthreads();
    }

    if (tid < NT2) {
        g_pn[(size_t)cid * NT2 + tid] = smf[U_PN + tid];
        g_pq[(size_t)cid * NT2 + tid] = smf[U_PQ + tid];
    }
}

// ==================== reduce / epilogue kernels ====================

__global__ void top1_kernel() {
    int w = (blockIdx.x * blockDim.x + threadIdx.x) >> 5;
    int lane = threadIdx.x & 31;
    if (w >= B_ * Q_ * N_) return;
    int nn = w % N_;
    int bq = w / N_;
    int bb = bq / Q_;
    int bn = bb * N_ + nn;
    float local = -INFINITY;
    for (int t = lane; t < T_; t += 32) {
        float num = g_pn[(size_t)(2 * w) * NT2 + t] + g_pn[(size_t)(2 * w + 1) * NT2 + t];
        float nrm = g_pq[(size_t)(2 * w) * NT2 + t] + g_pq[(size_t)(2 * w + 1) * NT2 + t];
        float denom = fmaxf(sqrtf(nrm) * g_nfs[bn * T_ + t], 1e-8f);
        local = fmaxf(local, num / denom);
    }
    #pragma unroll
    for (int o = 16; o > 0; o >>= 1)
        local = fmaxf(local, __shfl_xor_sync(0xffffffffu, local, o));
    if (lane == 0) g_top1[w] = local;
}

__global__ void finalize_logits_kernel(float* __restrict__ out) {
    int i = blockIdx.x * blockDim.x + threadIdx.x;
    if (i < B_ * Q_) {
        float s = 0.f;
        #pragma unroll
        for (int n = 0; n < N_; n++) s += g_top1[i * N_ + n];
        out[i] = s * (1.0f / N_);
    }
}

__global__ void cls_kernel(const float* __restrict__ xq,
                           const float* __restrict__ xs,
                           float* __restrict__ out) {
    int w = (blockIdx.x * blockDim.x + threadIdx.x) >> 5;
    int lid = threadIdx.x & 31;
    if (w >= B_ * Q_ * N_) return;
    int nn = w % N_;
    int qq = (w / N_) % Q_;
    int bb = w / (N_ * Q_);
    const float* q = xq + (size_t)(bb * Q_ + qq) * D_;
    const float* s = xs + (size_t)(bb * N_ + nn) * D_;
    float dot = 0.f, nq = 0.f, ns = 0.f;
    #pragma unroll
    for (int u = 0; u < D_ / 32; u++) {
        float a = q[lid + 32 * u];
        float b = s[lid + 32 * u];
        dot += a * b;
        nq += a * a;
        ns += b * b;
    }
    #pragma unroll
    for (int o = 16; o > 0; o >>= 1) {
        dot += __shfl_xor_sync(0xffffffffu, dot, o);
        nq  += __shfl_xor_sync(0xffffffffu, nq, o);
        ns  += __shfl_xor_sync(0xffffffffu, ns, o);
    }
    if (lid == 0) {
        float den = fmaxf(sqrtf(nq), 1e-12f) * fmaxf(sqrtf(ns), 1e-12f);
        out[B_ * Q_ + w] = 10.0f * dot / den;
    }
}

extern "C" void kernel_launch(void* const* d_in, const int* in_sizes, int n_in,
                              void* d_out, int out_size) {
    const float* fq = (const float*)d_in[0];
    const float* fs = (const float*)d_in[1];
    const float* xq = (const float*)d_in[2];
    const float* xs = (const float*)d_in[3];
    float* out = (float*)d_out;

    pack_a1<<<150 * NSLAB * KP1, 256>>>(fq);
    pack_b1<<<10 * KP1, 256>>>(fs);
    pack_b2<<<150 * KP2, 256>>>(fq);
    fsnorm_kernel<<<70, 256>>>(fs);

    const size_t smem_bytes = (size_t)U_TOT * sizeof(u32);
    cudaFuncSetAttribute(episodic_main,
                         cudaFuncAttributeMaxDynamicSharedMemorySize,
                         (int)smem_bytes);
    episodic_main<<<1500, TPB, smem_bytes>>>(fs);

    top1_kernel<<<(B_ * Q_ * N_ * 32 + 255) / 256, 256>>>();
    finalize_logits_kernel<<<1, 256>>>(out);
    cls_kernel<<<(B_ * Q_ * N_ * 32 + 255) / 256, 256>>>(xq, xs, out);
}

// round 13
// speedup vs baseline: 1.6258x; 1.2927x over previous
#include <cuda_runtime.h>
#include <cuda_fp16.h>
#include <math.h>
#include <stdint.h>

typedef unsigned int u32;

#define B_ 2
#define Q_ 75
#define N_ 5
#define T_ 196
#define C_ 384
#define D_ 384
#define SCALE (1.0f / 14.0f)

#define TPB 256
#define DT 32
#define NSLAB 12
#define HSLAB 6
#define KP1 13
#define KP2 24
#define NT2 200

#define A1_PANEL 256     // [T2][lane32][reg4] fp16x2
#define B1_PANEL 3072    // [G48][lane32][reg2] fp16x2 hi only
#define B2_PANEL 1600    // [G25][lane32][reg2] fp16x2 hi only

__device__ u32 g_A1[150 * NSLAB * KP1 * A1_PANEL];
__device__ u32 g_B1[10 * KP1 * B1_PANEL];
__device__ u32 g_B2[150 * KP2 * B2_PANEL];
__device__ float g_pn[1500 * NT2];
__device__ float g_pq[1500 * NT2];
__device__ float g_nfs[10 * T_];
__device__ float g_top1[B_ * Q_ * N_];

// smem layout (u32 offsets)
#define U_A2   0                         // [p24][mt2][lane32][r4] = 6144
#define U_B    6144                      // dbuf 2*3072
#define U_A1   (U_B + 2 * B1_PANEL)      // 12288: dbuf 2*256
#define U_PN   (U_A1 + 2 * A1_PANEL)     // 12800
#define U_PQ   (U_PN + NT2)
#define U_RINV (U_PQ + NT2)
#define U_PMAX (U_RINV + 32)
#define U_PSUM (U_PMAX + 256)
#define U_TOT  (U_PSUM + 256)            // 13744 u32 = 54976 B

__device__ __forceinline__ u32 hpack(float x0, float x1) {
    __half2 h; h.x = __float2half_rn(x0); h.y = __float2half_rn(x1);
    return *(u32*)&h;
}

__device__ __forceinline__ void mma16(float* c, const u32* a, u32 b0, u32 b1) {
    asm volatile(
        "mma.sync.aligned.m16n8k16.row.col.f32.f16.f16.f32 "
        "{%0,%1,%2,%3},{%4,%5,%6,%7},{%8,%9},{%0,%1,%2,%3};"
        : "+f"(c[0]), "+f"(c[1]), "+f"(c[2]), "+f"(c[3])
        : "r"(a[0]), "r"(a[1]), "r"(a[2]), "r"(a[3]), "r"(b0), "r"(b1));
}

__device__ __forceinline__ void cp16(u32 daddr, const void* src) {
    asm volatile("cp.async.cg.shared.global [%0], [%1], 16;" :: "r"(daddr), "l"(src));
}
#define CP_COMMIT() asm volatile("cp.async.commit_group;" ::: "memory")
#define CP_WAIT0()  asm volatile("cp.async.wait_group 0;" ::: "memory")

// ==================== pack kernels ====================

// A1[m=d][k=t] = SCALE * Fq[t][d], fp16, frag layout [T2][lane32][reg4]
__global__ void pack_a1(const float* __restrict__ fq) {
    __shared__ float tile[16][33];
    int bid = blockIdx.x;
    int p  = bid % KP1;
    int s  = (bid / KP1) % NSLAB;
    int bq = bid / (KP1 * NSLAB);
    const float* Fq = fq + (size_t)bq * T_ * C_;
    int d0 = s * DT;
    for (int idx = threadIdx.x; idx < 16 * DT; idx += 256) {
        int k = idx >> 5, d = idx & 31;
        int t = p * 16 + k;
        tile[k][d] = (t < T_) ? SCALE * Fq[(size_t)t * C_ + d0 + d] : 0.f;
    }
    __syncthreads();
    u32* dst = g_A1 + (size_t)bid * A1_PANEL;
    if (threadIdx.x < A1_PANEL) {
        int idx = threadIdx.x;
        int T   = (idx >> 7) & 1;
        int lane = (idx >> 2) & 31;
        int reg  = idx & 3;
        int grr = lane >> 2, gcc = lane & 3;
        int dl = T * 16 + grr + ((reg & 1) ? 8 : 0);
        int kl = 2 * gcc + ((reg & 2) ? 8 : 0);
        dst[idx] = hpack(tile[kl][dl], tile[kl + 1][dl]);
    }
}

// B1[k=t][n=c] = Fs[t][c], fp16 hi only, layout [G48][lane32][reg2]
__global__ void pack_b1(const float* __restrict__ fs) {
    __shared__ float tile[16][385];
    int bid = blockIdx.x;
    int p  = bid % KP1;
    int bn = bid / KP1;
    const float* Fs = fs + (size_t)bn * T_ * C_;
    for (int idx = threadIdx.x; idx < 16 * C_; idx += 256) {
        int k = idx / C_, c = idx % C_;
        int t = p * 16 + k;
        tile[k][c] = (t < T_) ? Fs[(size_t)t * C_ + c] : 0.f;
    }
    __syncthreads();
    u32* dst = g_B1 + (size_t)bid * B1_PANEL;
    for (int idx = threadIdx.x; idx < B1_PANEL; idx += 256) {
        int G    = idx >> 6;
        int lane = (idx >> 1) & 31;
        int reg  = idx & 1;
        int grr = lane >> 2, gcc = lane & 3;
        int n  = G * 8 + grr;
        int kl = 2 * gcc + 8 * reg;
        dst[idx] = hpack(tile[kl][n], tile[kl + 1][n]);
    }
}

// B2[k=c][n=t] = Fq[t][c], fp16 hi only, layout [G25][lane32][reg2]
__global__ void pack_b2(const float* __restrict__ fq) {
    __shared__ float tile[T_][17];
    int bid = blockIdx.x;
    int p  = bid % KP2;
    int bq = bid / KP2;
    const float* Fq = fq + (size_t)bq * T_ * C_;
    for (int idx = threadIdx.x; idx < T_ * 16; idx += 256) {
        int t = idx >> 4, c = idx & 15;
        tile[t][c] = Fq[(size_t)t * C_ + p * 16 + c];
    }
    __syncthreads();
    u32* dst = g_B2 + (size_t)bid * B2_PANEL;
    for (int idx = threadIdx.x; idx < B2_PANEL; idx += 256) {
        int G    = idx >> 6;
        int lane = (idx >> 1) & 31;
        int reg  = idx & 1;
        int grr = lane >> 2, gcc = lane & 3;
        int t  = G * 8 + grr;
        int kl = 2 * gcc + 8 * reg;
        float x0 = 0.f, x1 = 0.f;
        if (t < T_) { x0 = tile[t][kl]; x1 = tile[t][kl + 1]; }
        dst[idx] = hpack(x0, x1);
    }
}

__global__ void fsnorm_kernel(const float* __restrict__ fs) {
    int bn = blockIdx.x / 7;
    int base = (blockIdx.x % 7) * 28;
    int wid = threadIdx.x >> 5, lane = threadIdx.x & 31;
    const float* Fs = fs + (size_t)bn * T_ * C_;
    for (int r = base + wid; r < base + 28 && r < T_; r += 8) {
        float s = 0.f;
        #pragma unroll
        for (int u = 0; u < 12; u++) {
            float v = Fs[(size_t)r * C_ + lane + 32 * u];
            s += v * v;
        }
        #pragma unroll
        for (int o = 16; o > 0; o >>= 1) s += __shfl_xor_sync(0xffffffffu, s, o);
        if (lane == 0) g_nfs[bn * T_ + r] = sqrtf(s);
    }
}

// ==================== main kernel ====================

__global__ __launch_bounds__(TPB, 2)
void episodic_main(const float* __restrict__ fs_g) {
    extern __shared__ u32 smu[];
    float* smf = (float*)smu;
    const u32 smbase = (u32)__cvta_generic_to_shared(smu);

    const int cid = blockIdx.x;
    const int bx = cid >> 1;
    const int half = cid & 1;
    const int nn = bx % N_;
    const int bq = bx / N_;
    const int bb = bq / Q_;
    const int bn = bb * N_ + nn;
    const float* __restrict__ Fs = fs_g + (size_t)bn * T_ * C_;

    const int tid = threadIdx.x;
    const int wid = tid >> 5, lane = tid & 31;
    const int gr = lane >> 2, gc = lane & 3;
    const int ng2 = (wid == 0) ? 4 : 3;
    const int g2base = (wid == 0) ? 0 : 4 + (wid - 1) * 3;

    for (int i = tid; i < NT2; i += TPB) { smf[U_PN + i] = 0.f; smf[U_PQ + i] = 0.f; }
    __syncthreads();

    const u32* gB1 = g_B1 + (size_t)bn * KP1 * B1_PANEL;
    const u32* gB2 = g_B2 + (size_t)bq * KP2 * B2_PANEL;

    for (int s = 0; s < HSLAB; s++) {
        const int slab = half * HSLAB + s;
        const int d0 = slab * DT;
        const u32* gA1 = g_A1 + (size_t)(bq * NSLAB + slab) * KP1 * A1_PANEL;

        // ---------------- GEMM1 ----------------
        float acc1[2][6][4];
        #pragma unroll
        for (int mt = 0; mt < 2; mt++)
            #pragma unroll
            for (int nt = 0; nt < 6; nt++)
                #pragma unroll
                for (int e = 0; e < 4; e++) acc1[mt][nt][e] = 0.f;

        {
            const float4* srcB = (const float4*)(gB1);
            u32 dstB = smbase + (U_B) * 4;
            #pragma unroll
            for (int j = 0; j < 3; j++) cp16(dstB + (tid + j * TPB) * 16, srcB + tid + j * TPB);
            if (tid < 64) cp16(smbase + (U_A1) * 4 + tid * 16, ((const float4*)gA1) + tid);
            CP_COMMIT();
        }
        for (int p = 0; p < KP1; p++) {
            const int buf = p & 1;
            CP_WAIT0();
            __syncthreads();
            if (p + 1 < KP1) {
                const float4* srcB = (const float4*)(gB1 + (size_t)(p + 1) * B1_PANEL);
                u32 dstB = smbase + (U_B + (buf ^ 1) * B1_PANEL) * 4;
                #pragma unroll
                for (int j = 0; j < 3; j++) cp16(dstB + (tid + j * TPB) * 16, srcB + tid + j * TPB);
                if (tid < 64)
                    cp16(smbase + (U_A1 + (buf ^ 1) * A1_PANEL) * 4 + tid * 16,
                         ((const float4*)(gA1 + (size_t)(p + 1) * A1_PANEL)) + tid);
                CP_COMMIT();
            }
            const u32* bA = smu + U_A1 + buf * A1_PANEL;
            const u32* bB = smu + U_B + buf * B1_PANEL;
            u32 ah[2][4];
            #pragma unroll
            for (int mt = 0; mt < 2; mt++) {
                uint4 h = *(const uint4*)&bA[(mt * 32 + lane) * 4];
                ah[mt][0] = h.x; ah[mt][1] = h.y; ah[mt][2] = h.z; ah[mt][3] = h.w;
            }
            // single-term fp16: 12 mma / panel / warp
            #pragma unroll
            for (int np = 0; np < 3; np++) {
                int G0 = wid * 6 + 2 * np;
                uint2 b0 = *(const uint2*)&bB[(G0 * 32 + lane) * 2];
                uint2 b1 = *(const uint2*)&bB[((G0 + 1) * 32 + lane) * 2];
                #pragma unroll
                for (int mt = 0; mt < 2; mt++) mma16(acc1[mt][2 * np],     ah[mt], b0.x, b0.y);
                #pragma unroll
                for (int mt = 0; mt < 2; mt++) mma16(acc1[mt][2 * np + 1], ah[mt], b1.x, b1.y);
            }
        }

        // ---------------- softmax ----------------
        #pragma unroll
        for (int mt = 0; mt < 2; mt++)
            #pragma unroll
            for (int h = 0; h < 2; h++) {
                float mx = -INFINITY;
                #pragma unroll
                for (int nt = 0; nt < 6; nt++)
                    mx = fmaxf(mx, fmaxf(acc1[mt][nt][2 * h], acc1[mt][nt][2 * h + 1]));
                mx = fmaxf(mx, __shfl_xor_sync(0xffffffffu, mx, 1));
                mx = fmaxf(mx, __shfl_xor_sync(0xffffffffu, mx, 2));
                int row = mt * 16 + gr + 8 * h;
                if (gc == 0) smf[U_PMAX + row * 8 + wid] = mx;
            }
        __syncthreads();
        #pragma unroll
        for (int mt = 0; mt < 2; mt++)
            #pragma unroll
            for (int h = 0; h < 2; h++) {
                int row = mt * 16 + gr + 8 * h;
                float gmax = -INFINITY;
                #pragma unroll
                for (int w = 0; w < 8; w++)
                    gmax = fmaxf(gmax, smf[U_PMAX + row * 8 + w]);
                float s2 = 0.f;
                #pragma unroll
                for (int nt = 0; nt < 6; nt++) {
                    float v0 = __expf(acc1[mt][nt][2 * h] - gmax);
                    float v1 = __expf(acc1[mt][nt][2 * h + 1] - gmax);
                    acc1[mt][nt][2 * h] = v0;
                    acc1[mt][nt][2 * h + 1] = v1;
                    s2 += v0 + v1;
                }
                s2 += __shfl_xor_sync(0xffffffffu, s2, 1);
                s2 += __shfl_xor_sync(0xffffffffu, s2, 2);
                if (gc == 0) smf[U_PSUM + row * 8 + wid] = s2;
            }
        __syncthreads();
        if (wid == 0 && gc == 0) {
            #pragma unroll
            for (int mt = 0; mt < 2; mt++)
                #pragma unroll
                for (int h = 0; h < 2; h++) {
                    int row = mt * 16 + gr + 8 * h;
                    float tot = 0.f;
                    #pragma unroll
                    for (int w = 0; w < 8; w++) tot += smf[U_PSUM + row * 8 + w];
                    smf[U_RINV + row] = 1.0f / tot;
                }
        }

        // pack Pexp (fp16) into GEMM2 A-fragment layout
        #pragma unroll
        for (int mt = 0; mt < 2; mt++) {
            #pragma unroll
            for (int np = 0; np < 3; np++) {
                int G0 = wid * 6 + 2 * np;
                int p  = G0 >> 1;
                u32 vh0 = hpack(acc1[mt][2 * np][0], acc1[mt][2 * np][1]);
                u32 vh1 = hpack(acc1[mt][2 * np][2], acc1[mt][2 * np][3]);
                u32 vh2 = hpack(acc1[mt][2 * np + 1][0], acc1[mt][2 * np + 1][1]);
                u32 vh3 = hpack(acc1[mt][2 * np + 1][2], acc1[mt][2 * np + 1][3]);
                *(uint4*)&smu[U_A2 + ((p * 2 + mt) * 32 + lane) * 4] =
                    make_uint4(vh0, vh1, vh2, vh3);
            }
        }
        __syncthreads();

        // ---------------- GEMM2 ----------------
        float acc2[2][4][4];
        #pragma unroll
        for (int mt = 0; mt < 2; mt++)
            #pragma unroll
            for (int nt = 0; nt < 4; nt++)
                #pragma unroll
                for (int e = 0; e < 4; e++) acc2[mt][nt][e] = 0.f;

        {
            const float4* srcB = (const float4*)(gB2);
            u32 dstB = smbase + (U_B) * 4;
            #pragma unroll
            for (int j = 0; j < 2; j++) {
                int i = tid + j * TPB;
                if (i < 400) cp16(dstB + i * 16, srcB + i);
            }
            CP_COMMIT();
        }
        for (int p = 0; p < KP2; p++) {
            const int buf = p & 1;
            CP_WAIT0();
            __syncthreads();
            if (p + 1 < KP2) {
                const float4* srcB = (const float4*)(gB2 + (size_t)(p + 1) * B2_PANEL);
                u32 dstB = smbase + (U_B + (buf ^ 1) * B1_PANEL) * 4;
                #pragma unroll
                for (int j = 0; j < 2; j++) {
                    int i = tid + j * TPB;
                    if (i < 400) cp16(dstB + i * 16, srcB + i);
                }
                CP_COMMIT();
            }
            const u32* bB = smu + U_B + buf * B1_PANEL;
            u32 ah[2][4];
            #pragma unroll
            for (int mt = 0; mt < 2; mt++) {
                uint4 h = *(const uint4*)&smu[U_A2 + ((p * 2 + mt) * 32 + lane) * 4];
                ah[mt][0] = h.x; ah[mt][1] = h.y; ah[mt][2] = h.z; ah[mt][3] = h.w;
            }
            for (int nt = 0; nt < ng2; nt++) {
                int G = g2base + nt;
                uint2 b2 = *(const uint2*)&bB[(G * 32 + lane) * 2];
                #pragma unroll
                for (int mt = 0; mt < 2; mt++) mma16(acc2[mt][nt], ah[mt], b2.x, b2.y);
            }
        }
        __syncthreads();

        // ---------------- epilogue ----------------
        for (int nt = 0; nt < ng2; nt++) {
            int G = g2base + nt;
            int ta = G * 8 + 2 * gc;
            int tb = ta + 1;
            float pn_a = 0.f, pq_a = 0.f, pn_b = 0.f, pq_b = 0.f;
            #pragma unroll
            for (int mt = 0; mt < 2; mt++) {
                int rb1 = mt * 16 + gr;
                int rb2 = rb1 + 8;
                float r1 = smf[U_RINV + rb1];
                float r2 = smf[U_RINV + rb2];
                float v0 = acc2[mt][nt][0] * r1;
                float v1 = acc2[mt][nt][1] * r1;
                float v2 = acc2[mt][nt][2] * r2;
                float v3 = acc2[mt][nt][3] * r2;
                int gd1 = d0 + rb1, gd2 = d0 + rb2;
                float fa1 = 0.f, fa2 = 0.f, fb1 = 0.f, fb2 = 0.f;
                if (ta < T_) { fa1 = Fs[(size_t)ta * C_ + gd1]; fa2 = Fs[(size_t)ta * C_ + gd2]; }
                if (tb < T_) { fb1 = Fs[(size_t)tb * C_ + gd1]; fb2 = Fs[(size_t)tb * C_ + gd2]; }
                pn_a += v0 * fa1 + v2 * fa2;
                pq_a += v0 * v0 + v2 * v2;
                pn_b += v1 * fb1 + v3 * fb2;
                pq_b += v1 * v1 + v3 * v3;
            }
            #pragma unroll
            for (int o = 4; o <= 16; o <<= 1) {
                pn_a += __shfl_xor_sync(0xffffffffu, pn_a, o);
                pq_a += __shfl_xor_sync(0xffffffffu, pq_a, o);
                pn_b += __shfl_xor_sync(0xffffffffu, pn_b, o);
                pq_b += __shfl_xor_sync(0xffffffffu, pq_b, o);
            }
            if (lane < 4) {
                smf[U_PN + ta] += pn_a;
                smf[U_PQ + ta] += pq_a;
                smf[U_PN + tb] += pn_b;
                smf[U_PQ + tb] += pq_b;
            }
        }
        __syncthreads();
    }

    if (tid < NT2) {
        g_pn[(size_t)cid * NT2 + tid] = smf[U_PN + tid];
        g_pq[(size_t)cid * NT2 + tid] = smf[U_PQ + tid];
    }
}

// ==================== reduce / epilogue kernels ====================

__global__ void top1_kernel() {
    int w = (blockIdx.x * blockDim.x + threadIdx.x) >> 5;
    int lane = threadIdx.x & 31;
    if (w >= B_ * Q_ * N_) return;
    int nn = w % N_;
    int bq = w / N_;
    int bb = bq / Q_;
    int bn = bb * N_ + nn;
    float local = -INFINITY;
    for (int t = lane; t < T_; t += 32) {
        float num = g_pn[(size_t)(2 * w) * NT2 + t] + g_pn[(size_t)(2 * w + 1) * NT2 + t];
        float nrm = g_pq[(size_t)(2 * w) * NT2 + t] + g_pq[(size_t)(2 * w + 1) * NT2 + t];
        float denom = fmaxf(sqrtf(nrm) * g_nfs[bn * T_ + t], 1e-8f);
        local = fmaxf(local, num / denom);
    }
    #pragma unroll
    for (int o = 16; o > 0; o >>= 1)
        local = fmaxf(local, __shfl_xor_sync(0xffffffffu, local, o));
    if (lane == 0) g_top1[w] = local;
}

__global__ void finalize_logits_kernel(float* __restrict__ out) {
    int i = blockIdx.x * blockDim.x + threadIdx.x;
    if (i < B_ * Q_) {
        float s = 0.f;
        #pragma unroll
        for (int n = 0; n < N_; n++) s += g_top1[i * N_ + n];
        out[i] = s * (1.0f / N_);
    }
}

__global__ void cls_kernel(const float* __restrict__ xq,
                           const float* __restrict__ xs,
                           float* __restrict__ out) {
    int w = (blockIdx.x * blockDim.x + threadIdx.x) >> 5;
    int lid = threadIdx.x & 31;
    if (w >= B_ * Q_ * N_) return;
    int nn = w % N_;
    int qq = (w / N_) % Q_;
    int bb = w / (N_ * Q_);
    const float* q = xq + (size_t)(bb * Q_ + qq) * D_;
    const float* s = xs + (size_t)(bb * N_ + nn) * D_;
    float dot = 0.f, nq = 0.f, ns = 0.f;
    #pragma unroll
    for (int u = 0; u < D_ / 32; u++) {
        float a = q[lid + 32 * u];
        float b = s[lid + 32 * u];
        dot += a * b;
        nq += a * a;
        ns += b * b;
    }
    #pragma unroll
    for (int o = 16; o > 0; o >>= 1) {
        dot += __shfl_xor_sync(0xffffffffu, dot, o);
        nq  += __shfl_xor_sync(0xffffffffu, nq, o);
        ns  += __shfl_xor_sync(0xffffffffu, ns, o);
    }
    if (lid == 0) {
        float den = fmaxf(sqrtf(nq), 1e-12f) * fmaxf(sqrtf(ns), 1e-12f);
        out[B_ * Q_ + w] = 10.0f * dot / den;
    }
}

extern "C" void kernel_launch(void* const* d_in, const int* in_sizes, int n_in,
                              void* d_out, int out_size) {
    const float* fq = (const float*)d_in[0];
    const float* fs = (const float*)d_in[1];
    const float* xq = (const float*)d_in[2];
    const float* xs = (const float*)d_in[3];
    float* out = (float*)d_out;

    pack_a1<<<150 * NSLAB * KP1, 256>>>(fq);
    pack_b1<<<10 * KP1, 256>>>(fs);
    pack_b2<<<150 * KP2, 256>>>(fq);
    fsnorm_kernel<<<70, 256>>>(fs);

    const size_t smem_bytes = (size_t)U_TOT * sizeof(u32);
    cudaFuncSetAttribute(episodic_main,
                         cudaFuncAttributeMaxDynamicSharedMemorySize,
                         (int)smem_bytes);
    episodic_main<<<1500, TPB, smem_bytes>>>(fs);

    top1_kernel<<<(B_ * Q_ * N_ * 32 + 255) / 256, 256>>>();
    finalize_logits_kernel<<<1, 256>>>(out);
    cls_kernel<<<(B_ * Q_ * N_ * 32 + 255) / 256, 256>>>(xq, xs, out);
}

// round 14
// speedup vs baseline: 1.8013x; 1.1080x over previous
#include <cuda_runtime.h>
#include <cuda_fp16.h>
#include <math.h>
#include <stdint.h>

typedef unsigned int u32;

#define B_ 2
#define Q_ 75
#define N_ 5
#define T_ 196
#define C_ 384
#define D_ 384
#define SCALE (1.0f / 14.0f)

#define TPB 256
#define DT 32
#define NSLAB 12
#define HSLAB 6
#define KP1 13
#define KP2 24
#define NT2 200

#define A1_PANEL 256     // [T2][lane32][reg4] fp16x2
#define B1_PANEL 3072    // [G48][lane32][reg2] fp16x2
#define B2_PANEL 1600    // [G25][lane32][reg2] fp16x2

__device__ u32 g_A1[150 * NSLAB * KP1 * A1_PANEL];
__device__ u32 g_B1[10 * KP1 * B1_PANEL];
__device__ u32 g_B2[150 * KP2 * B2_PANEL];
__device__ float g_pn[1500 * NT2];
__device__ float g_pq[1500 * NT2];
__device__ float g_nfs[10 * T_];

// smem layout (u32 offsets)
#define U_A2   0                         // [p24][mt2][lane32][r4] = 6144
#define U_B    6144                      // dbuf 2 x (2 panels): 12288
#define U_A1   (U_B + 4 * B1_PANEL)      // 18432: dbuf 2 x 512
#define U_PN   (U_A1 + 4 * A1_PANEL)     // 19456
#define U_PQ   (U_PN + NT2)
#define U_RINV (U_PQ + NT2)
#define U_PMAX (U_RINV + 32)
#define U_PSUM (U_PMAX + 256)
#define U_TOT  (U_PSUM + 256)            // 20400 u32 = 81600 B

__device__ __forceinline__ u32 hpack(float x0, float x1) {
    __half2 h; h.x = __float2half_rn(x0); h.y = __float2half_rn(x1);
    return *(u32*)&h;
}

__device__ __forceinline__ void mma16(float* c, const u32* a, u32 b0, u32 b1) {
    asm volatile(
        "mma.sync.aligned.m16n8k16.row.col.f32.f16.f16.f32 "
        "{%0,%1,%2,%3},{%4,%5,%6,%7},{%8,%9},{%0,%1,%2,%3};"
        : "+f"(c[0]), "+f"(c[1]), "+f"(c[2]), "+f"(c[3])
        : "r"(a[0]), "r"(a[1]), "r"(a[2]), "r"(a[3]), "r"(b0), "r"(b1));
}

__device__ __forceinline__ void cp16(u32 daddr, const void* src) {
    asm volatile("cp.async.cg.shared.global [%0], [%1], 16;" :: "r"(daddr), "l"(src));
}
#define CP_COMMIT() asm volatile("cp.async.commit_group;" ::: "memory")
#define CP_WAIT0()  asm volatile("cp.async.wait_group 0;" ::: "memory")

// ==================== merged pack kernel ====================
// blocks: [0,23400) pack_a1 | [23400,23530) pack_b1 | [23530,27130) pack_b2 | [27130,27200) fsnorm

#define NB_A1 (150 * NSLAB * KP1)
#define NB_B1 (10 * KP1)
#define NB_B2 (150 * KP2)

__global__ void pack_all(const float* __restrict__ fq, const float* __restrict__ fs) {
    __shared__ float buf[16 * 385];
    int bid = blockIdx.x;
    if (bid < NB_A1) {
        // A1[m=d][k=t] = SCALE * Fq[t][d], tile stride 33
        int p  = bid % KP1;
        int s  = (bid / KP1) % NSLAB;
        int bq = bid / (KP1 * NSLAB);
        const float* Fq = fq + (size_t)bq * T_ * C_;
        int d0 = s * DT;
        for (int idx = threadIdx.x; idx < 16 * DT; idx += 256) {
            int k = idx >> 5, d = idx & 31;
            int t = p * 16 + k;
            buf[k * 33 + d] = (t < T_) ? SCALE * Fq[(size_t)t * C_ + d0 + d] : 0.f;
        }
        __syncthreads();
        u32* dst = g_A1 + (size_t)bid * A1_PANEL;
        if (threadIdx.x < A1_PANEL) {
            int idx = threadIdx.x;
            int T   = (idx >> 7) & 1;
            int lane = (idx >> 2) & 31;
            int reg  = idx & 3;
            int grr = lane >> 2, gcc = lane & 3;
            int dl = T * 16 + grr + ((reg & 1) ? 8 : 0);
            int kl = 2 * gcc + ((reg & 2) ? 8 : 0);
            dst[idx] = hpack(buf[kl * 33 + dl], buf[(kl + 1) * 33 + dl]);
        }
    } else if (bid < NB_A1 + NB_B1) {
        // B1[k=t][n=c] = Fs[t][c], tile stride 385
        int b = bid - NB_A1;
        int p  = b % KP1;
        int bn = b / KP1;
        const float* Fs = fs + (size_t)bn * T_ * C_;
        for (int idx = threadIdx.x; idx < 16 * C_; idx += 256) {
            int k = idx / C_, c = idx % C_;
            int t = p * 16 + k;
            buf[k * 385 + c] = (t < T_) ? Fs[(size_t)t * C_ + c] : 0.f;
        }
        __syncthreads();
        u32* dst = g_B1 + (size_t)b * B1_PANEL;
        for (int idx = threadIdx.x; idx < B1_PANEL; idx += 256) {
            int G    = idx >> 6;
            int lane = (idx >> 1) & 31;
            int reg  = idx & 1;
            int grr = lane >> 2, gcc = lane & 3;
            int n  = G * 8 + grr;
            int kl = 2 * gcc + 8 * reg;
            dst[idx] = hpack(buf[kl * 385 + n], buf[(kl + 1) * 385 + n]);
        }
    } else if (bid < NB_A1 + NB_B1 + NB_B2) {
        // B2[k=c][n=t] = Fq[t][c], tile stride 17
        int b = bid - NB_A1 - NB_B1;
        int p  = b % KP2;
        int bq = b / KP2;
        const float* Fq = fq + (size_t)bq * T_ * C_;
        for (int idx = threadIdx.x; idx < T_ * 16; idx += 256) {
            int t = idx >> 4, c = idx & 15;
            buf[t * 17 + c] = Fq[(size_t)t * C_ + p * 16 + c];
        }
        __syncthreads();
        u32* dst = g_B2 + (size_t)b * B2_PANEL;
        for (int idx = threadIdx.x; idx < B2_PANEL; idx += 256) {
            int G    = idx >> 6;
            int lane = (idx >> 1) & 31;
            int reg  = idx & 1;
            int grr = lane >> 2, gcc = lane & 3;
            int t  = G * 8 + grr;
            int kl = 2 * gcc + 8 * reg;
            float x0 = 0.f, x1 = 0.f;
            if (t < T_) { x0 = buf[t * 17 + kl]; x1 = buf[t * 17 + kl + 1]; }
            dst[idx] = hpack(x0, x1);
        }
    } else {
        // fsnorm: 70 blocks (10 bn x 7 row-chunks of 28)
        int b = bid - NB_A1 - NB_B1 - NB_B2;
        int bn = b / 7;
        int base = (b % 7) * 28;
        int wid = threadIdx.x >> 5, lane = threadIdx.x & 31;
        const float* Fs = fs + (size_t)bn * T_ * C_;
        for (int r = base + wid; r < base + 28 && r < T_; r += 8) {
            float s = 0.f;
            #pragma unroll
            for (int u = 0; u < 12; u++) {
                float v = Fs[(size_t)r * C_ + lane + 32 * u];
                s += v * v;
            }
            #pragma unroll
            for (int o = 16; o > 0; o >>= 1) s += __shfl_xor_sync(0xffffffffu, s, o);
            if (lane == 0) g_nfs[bn * T_ + r] = sqrtf(s);
        }
    }
}

// ==================== main kernel ====================

__global__ __launch_bounds__(TPB, 2)
void episodic_main(const float* __restrict__ fs_g) {
    extern __shared__ u32 smu[];
    float* smf = (float*)smu;
    const u32 smbase = (u32)__cvta_generic_to_shared(smu);

    const int cid = blockIdx.x;
    const int bx = cid >> 1;
    const int half = cid & 1;
    const int nn = bx % N_;
    const int bq = bx / N_;
    const int bb = bq / Q_;
    const int bn = bb * N_ + nn;
    const float* __restrict__ Fs = fs_g + (size_t)bn * T_ * C_;

    const int tid = threadIdx.x;
    const int wid = tid >> 5, lane = tid & 31;
    const int gr = lane >> 2, gc = lane & 3;
    const int ng2 = (wid == 0) ? 4 : 3;
    const int g2base = (wid == 0) ? 0 : 4 + (wid - 1) * 3;

    for (int i = tid; i < NT2; i += TPB) { smf[U_PN + i] = 0.f; smf[U_PQ + i] = 0.f; }
    __syncthreads();

    const u32* gB1 = g_B1 + (size_t)bn * KP1 * B1_PANEL;
    const u32* gB2 = g_B2 + (size_t)bq * KP2 * B2_PANEL;

    for (int s = 0; s < HSLAB; s++) {
        const int slab = half * HSLAB + s;
        const int d0 = slab * DT;
        const u32* gA1 = g_A1 + (size_t)(bq * NSLAB + slab) * KP1 * A1_PANEL;

        // ---------------- GEMM1: 7 iterations of 2 panels ----------------
        float acc1[2][6][4];
        #pragma unroll
        for (int mt = 0; mt < 2; mt++)
            #pragma unroll
            for (int nt = 0; nt < 6; nt++)
                #pragma unroll
                for (int e = 0; e < 4; e++) acc1[mt][nt][e] = 0.f;

        {
            const float4* srcB = (const float4*)(gB1);
            u32 dstB = smbase + (U_B) * 4;
            for (int i = tid; i < 1536; i += TPB) cp16(dstB + i * 16, srcB + i);
            if (tid < 128) cp16(smbase + (U_A1) * 4 + tid * 16, ((const float4*)gA1) + tid);
            CP_COMMIT();
        }
        for (int it = 0; it < 7; it++) {
            const int buf = it & 1;
            CP_WAIT0();
            __syncthreads();
            if (it + 1 < 7) {
                int base = 2 * (it + 1);
                int npan_n = (base + 1 < KP1) ? 2 : 1;
                const float4* srcB = (const float4*)(gB1 + (size_t)base * B1_PANEL);
                u32 dstB = smbase + (U_B + (buf ^ 1) * 2 * B1_PANEL) * 4;
                int n4 = npan_n * (B1_PANEL / 4);
                for (int i = tid; i < n4; i += TPB) cp16(dstB + i * 16, srcB + i);
                const float4* srcA = (const float4*)(gA1 + (size_t)base * A1_PANEL);
                int na = npan_n * (A1_PANEL / 4);
                if (tid < na)
                    cp16(smbase + (U_A1 + (buf ^ 1) * 2 * A1_PANEL) * 4 + tid * 16, srcA + tid);
                CP_COMMIT();
            }
            int npan = (2 * it + 1 < KP1) ? 2 : 1;
            for (int sub = 0; sub < npan; sub++) {
                const u32* bA = smu + U_A1 + buf * 2 * A1_PANEL + sub * A1_PANEL;
                const u32* bB = smu + U_B + buf * 2 * B1_PANEL + sub * B1_PANEL;
                u32 ah[2][4];
                #pragma unroll
                for (int mt = 0; mt < 2; mt++) {
                    uint4 h = *(const uint4*)&bA[(mt * 32 + lane) * 4];
                    ah[mt][0] = h.x; ah[mt][1] = h.y; ah[mt][2] = h.z; ah[mt][3] = h.w;
                }
                #pragma unroll
                for (int np = 0; np < 3; np++) {
                    int G0 = wid * 6 + 2 * np;
                    uint2 b0 = *(const uint2*)&bB[(G0 * 32 + lane) * 2];
                    uint2 b1 = *(const uint2*)&bB[((G0 + 1) * 32 + lane) * 2];
                    #pragma unroll
                    for (int mt = 0; mt < 2; mt++) mma16(acc1[mt][2 * np],     ah[mt], b0.x, b0.y);
                    #pragma unroll
                    for (int mt = 0; mt < 2; mt++) mma16(acc1[mt][2 * np + 1], ah[mt], b1.x, b1.y);
                }
            }
        }

        // ---------------- softmax ----------------
        #pragma unroll
        for (int mt = 0; mt < 2; mt++)
            #pragma unroll
            for (int h = 0; h < 2; h++) {
                float mx = -INFINITY;
                #pragma unroll
                for (int nt = 0; nt < 6; nt++)
                    mx = fmaxf(mx, fmaxf(acc1[mt][nt][2 * h], acc1[mt][nt][2 * h + 1]));
                mx = fmaxf(mx, __shfl_xor_sync(0xffffffffu, mx, 1));
                mx = fmaxf(mx, __shfl_xor_sync(0xffffffffu, mx, 2));
                int row = mt * 16 + gr + 8 * h;
                if (gc == 0) smf[U_PMAX + row * 8 + wid] = mx;
            }
        __syncthreads();
        #pragma unroll
        for (int mt = 0; mt < 2; mt++)
            #pragma unroll
            for (int h = 0; h < 2; h++) {
                int row = mt * 16 + gr + 8 * h;
                float gmax = -INFINITY;
                #pragma unroll
                for (int w = 0; w < 8; w++)
                    gmax = fmaxf(gmax, smf[U_PMAX + row * 8 + w]);
                float s2 = 0.f;
                #pragma unroll
                for (int nt = 0; nt < 6; nt++) {
                    float v0 = __expf(acc1[mt][nt][2 * h] - gmax);
                    float v1 = __expf(acc1[mt][nt][2 * h + 1] - gmax);
                    acc1[mt][nt][2 * h] = v0;
                    acc1[mt][nt][2 * h + 1] = v1;
                    s2 += v0 + v1;
                }
                s2 += __shfl_xor_sync(0xffffffffu, s2, 1);
                s2 += __shfl_xor_sync(0xffffffffu, s2, 2);
                if (gc == 0) smf[U_PSUM + row * 8 + wid] = s2;
            }
        __syncthreads();
        if (wid == 0 && gc == 0) {
            #pragma unroll
            for (int mt = 0; mt < 2; mt++)
                #pragma unroll
                for (int h = 0; h < 2; h++) {
                    int row = mt * 16 + gr + 8 * h;
                    float tot = 0.f;
                    #pragma unroll
                    for (int w = 0; w < 8; w++) tot += smf[U_PSUM + row * 8 + w];
                    smf[U_RINV + row] = 1.0f / tot;
                }
        }

        // pack Pexp (fp16) into GEMM2 A-fragment layout
        #pragma unroll
        for (int mt = 0; mt < 2; mt++) {
            #pragma unroll
            for (int np = 0; np < 3; np++) {
                int G0 = wid * 6 + 2 * np;
                int p  = G0 >> 1;
                u32 vh0 = hpack(acc1[mt][2 * np][0], acc1[mt][2 * np][1]);
                u32 vh1 = hpack(acc1[mt][2 * np][2], acc1[mt][2 * np][3]);
                u32 vh2 = hpack(acc1[mt][2 * np + 1][0], acc1[mt][2 * np + 1][1]);
                u32 vh3 = hpack(acc1[mt][2 * np + 1][2], acc1[mt][2 * np + 1][3]);
                *(uint4*)&smu[U_A2 + ((p * 2 + mt) * 32 + lane) * 4] =
                    make_uint4(vh0, vh1, vh2, vh3);
            }
        }
        __syncthreads();

        // ---------------- GEMM2: 12 iterations of 2 panels ----------------
        float acc2[2][4][4];
        #pragma unroll
        for (int mt = 0; mt < 2; mt++)
            #pragma unroll
            for (int nt = 0; nt < 4; nt++)
                #pragma unroll
                for (int e = 0; e < 4; e++) acc2[mt][nt][e] = 0.f;

        {
            const float4* srcB = (const float4*)(gB2);
            u32 dstB = smbase + (U_B) * 4;
            for (int i = tid; i < 800; i += TPB) cp16(dstB + i * 16, srcB + i);
            CP_COMMIT();
        }
        for (int it = 0; it < 12; it++) {
            const int buf = it & 1;
            CP_WAIT0();
            __syncthreads();
            if (it + 1 < 12) {
                const float4* srcB = (const float4*)(gB2 + (size_t)(2 * it + 2) * B2_PANEL);
                u32 dstB = smbase + (U_B + (buf ^ 1) * 2 * B2_PANEL) * 4;
                for (int i = tid; i < 800; i += TPB) cp16(dstB + i * 16, srcB + i);
                CP_COMMIT();
            }
            #pragma unroll
            for (int sub = 0; sub < 2; sub++) {
                int p = 2 * it + sub;
                const u32* bB = smu + U_B + buf * 2 * B2_PANEL + sub * B2_PANEL;
                u32 ah[2][4];
                #pragma unroll
                for (int mt = 0; mt < 2; mt++) {
                    uint4 h = *(const uint4*)&smu[U_A2 + ((p * 2 + mt) * 32 + lane) * 4];
                    ah[mt][0] = h.x; ah[mt][1] = h.y; ah[mt][2] = h.z; ah[mt][3] = h.w;
                }
                for (int nt = 0; nt < ng2; nt++) {
                    int G = g2base + nt;
                    uint2 b2 = *(const uint2*)&bB[(G * 32 + lane) * 2];
                    #pragma unroll
                    for (int mt = 0; mt < 2; mt++) mma16(acc2[mt][nt], ah[mt], b2.x, b2.y);
                }
            }
        }
        __syncthreads();

        // ---------------- epilogue ----------------
        for (int nt = 0; nt < ng2; nt++) {
            int G = g2base + nt;
            int ta = G * 8 + 2 * gc;
            int tb = ta + 1;
            float pn_a = 0.f, pq_a = 0.f, pn_b = 0.f, pq_b = 0.f;
            #pragma unroll
            for (int mt = 0; mt < 2; mt++) {
                int rb1 = mt * 16 + gr;
                int rb2 = rb1 + 8;
                float r1 = smf[U_RINV + rb1];
                float r2 = smf[U_RINV + rb2];
                float v0 = acc2[mt][nt][0] * r1;
                float v1 = acc2[mt][nt][1] * r1;
                float v2 = acc2[mt][nt][2] * r2;
                float v3 = acc2[mt][nt][3] * r2;
                int gd1 = d0 + rb1, gd2 = d0 + rb2;
                float fa1 = 0.f, fa2 = 0.f, fb1 = 0.f, fb2 = 0.f;
                if (ta < T_) { fa1 = Fs[(size_t)ta * C_ + gd1]; fa2 = Fs[(size_t)ta * C_ + gd2]; }
                if (tb < T_) { fb1 = Fs[(size_t)tb * C_ + gd1]; fb2 = Fs[(size_t)tb * C_ + gd2]; }
                pn_a += v0 * fa1 + v2 * fa2;
                pq_a += v0 * v0 + v2 * v2;
                pn_b += v1 * fb1 + v3 * fb2;
                pq_b += v1 * v1 + v3 * v3;
            }
            #pragma unroll
            for (int o = 4; o <= 16; o <<= 1) {
                pn_a += __shfl_xor_sync(0xffffffffu, pn_a, o);
                pq_a += __shfl_xor_sync(0xffffffffu, pq_a, o);
                pn_b += __shfl_xor_sync(0xffffffffu, pn_b, o);
                pq_b += __shfl_xor_sync(0xffffffffu, pq_b, o);
            }
            if (lane < 4) {
                smf[U_PN + ta] += pn_a;
                smf[U_PQ + ta] += pq_a;
                smf[U_PN + tb] += pn_b;
                smf[U_PQ + tb] += pq_b;
            }
        }
        __syncthreads();
    }

    if (tid < NT2) {
        g_pn[(size_t)cid * NT2 + tid] = smf[U_PN + tid];
        g_pq[(size_t)cid * NT2 + tid] = smf[U_PQ + tid];
    }
}

// ==================== merged final kernel ====================
// warps [0,150): logits (top1 over t, mean over n) ; warps [150,900): cls

__global__ void final_kernel(const float* __restrict__ xq,
                             const float* __restrict__ xs,
                             float* __restrict__ out) {
    int gw = (blockIdx.x * blockDim.x + threadIdx.x) >> 5;
    int lane = threadIdx.x & 31;
    if (gw < B_ * Q_) {
        int bb = gw / Q_;
        float acc = 0.f;
        for (int n = 0; n < N_; n++) {
            int w = gw * N_ + n;
            int bn = bb * N_ + n;
            float local = -INFINITY;
            for (int t = lane; t < T_; t += 32) {
                float num = g_pn[(size_t)(2 * w) * NT2 + t] + g_pn[(size_t)(2 * w + 1) * NT2 + t];
                float nrm = g_pq[(size_t)(2 * w) * NT2 + t] + g_pq[(size_t)(2 * w + 1) * NT2 + t];
                float denom = fmaxf(sqrtf(nrm) * g_nfs[bn * T_ + t], 1e-8f);
                local = fmaxf(local, num / denom);
            }
            #pragma unroll
            for (int o = 16; o > 0; o >>= 1)
                local = fmaxf(local, __shfl_xor_sync(0xffffffffu, local, o));
            acc += local;
        }
        if (lane == 0) out[gw] = acc * (1.0f / N_);
    } else if (gw < B_ * Q_ + B_ * Q_ * N_) {
        int w = gw - B_ * Q_;
        int nn = w % N_;
        int qq = (w / N_) % Q_;
        int bb = w / (N_ * Q_);
        const float* q = xq + (size_t)(bb * Q_ + qq) * D_;
        const float* s = xs + (size_t)(bb * N_ + nn) * D_;
        float dot = 0.f, nq = 0.f, ns = 0.f;
        #pragma unroll
        for (int u = 0; u < D_ / 32; u++) {
            float a = q[lane + 32 * u];
            float b = s[lane + 32 * u];
            dot += a * b;
            nq += a * a;
            ns += b * b;
        }
        #pragma unroll
        for (int o = 16; o > 0; o >>= 1) {
            dot += __shfl_xor_sync(0xffffffffu, dot, o);
            nq  += __shfl_xor_sync(0xffffffffu, nq, o);
            ns  += __shfl_xor_sync(0xffffffffu, ns, o);
        }
        if (lane == 0) {
            float den = fmaxf(sqrtf(nq), 1e-12f) * fmaxf(sqrtf(ns), 1e-12f);
            out[B_ * Q_ + w] = 10.0f * dot / den;
        }
    }
}

extern "C" void kernel_launch(void* const* d_in, const int* in_sizes, int n_in,
                              void* d_out, int out_size) {
    const float* fq = (const float*)d_in[0];
    const float* fs = (const float*)d_in[1];
    const float* xq = (const float*)d_in[2];
    const float* xs = (const float*)d_in[3];
    float* out = (float*)d_out;

    pack_all<<<NB_A1 + NB_B1 + NB_B2 + 70, 256>>>(fq, fs);

    const size_t smem_bytes = (size_t)U_TOT * sizeof(u32);
    cudaFuncSetAttribute(episodic_main,
                         cudaFuncAttributeMaxDynamicSharedMemorySize,
                         (int)smem_bytes);
    episodic_main<<<1500, TPB, smem_bytes>>>(fs);

    final_kernel<<<(900 * 32 + 255) / 256, 256>>>(xq, xs, out);
}

// round 15
// speedup vs baseline: 1.9435x; 1.0789x over previous
#include <cuda_runtime.h>
#include <cuda_fp16.h>
#include <math.h>
#include <stdint.h>

typedef unsigned int u32;

#define B_ 2
#define Q_ 75
#define N_ 5
#define T_ 196
#define C_ 384
#define D_ 384
#define SCALE (1.0f / 14.0f)

#define TPB 256
#define DT 32
#define NSLAB 12
#define HSLAB 6
#define KP1 13
#define KP2 24
#define NT2 200

#define A1_PANEL 256     // [T2][lane32][reg4] fp16x2
#define B1_PANEL 3072    // [G48][lane32][reg2] fp16x2
#define B2_PANEL 1600    // [G25][lane32][reg2] fp16x2
#define U_BSZ 6400       // staging buffer region (max(2*B1P, 4*B2P))

__device__ u32 g_A1[150 * NSLAB * KP1 * A1_PANEL];
__device__ u32 g_B1[10 * KP1 * B1_PANEL];
__device__ u32 g_B2[150 * KP2 * B2_PANEL];
__device__ float g_pn[1500 * NT2];
__device__ float g_pq[1500 * NT2];
__device__ float g_nfs[10 * T_];

// smem layout (u32 offsets)
#define U_A2   0                         // [p24][mt2][lane32][r4] = 6144
#define U_B    6144                      // dbuf 2 x U_BSZ = 12800
#define U_A1   (U_B + 2 * U_BSZ)         // 18944: dbuf 2 x 512
#define U_PN   (U_A1 + 4 * A1_PANEL)     // 19968
#define U_PQ   (U_PN + NT2)
#define U_RINV (U_PQ + NT2)
#define U_PMAX (U_RINV + 32)
#define U_PSUM (U_PMAX + 256)
#define U_TOT  (U_PSUM + 256)            // 20912 u32 = 83648 B

__device__ __forceinline__ u32 hpack(float x0, float x1) {
    __half2 h; h.x = __float2half_rn(x0); h.y = __float2half_rn(x1);
    return *(u32*)&h;
}

__device__ __forceinline__ void mma16(float* c, const u32* a, u32 b0, u32 b1) {
    asm volatile(
        "mma.sync.aligned.m16n8k16.row.col.f32.f16.f16.f32 "
        "{%0,%1,%2,%3},{%4,%5,%6,%7},{%8,%9},{%0,%1,%2,%3};"
        : "+f"(c[0]), "+f"(c[1]), "+f"(c[2]), "+f"(c[3])
        : "r"(a[0]), "r"(a[1]), "r"(a[2]), "r"(a[3]), "r"(b0), "r"(b1));
}

__device__ __forceinline__ void cp16(u32 daddr, const void* src) {
    asm volatile("cp.async.cg.shared.global [%0], [%1], 16;" :: "r"(daddr), "l"(src));
}
#define CP_COMMIT() asm volatile("cp.async.commit_group;" ::: "memory")
#define CP_WAIT0()  asm volatile("cp.async.wait_group 0;" ::: "memory")

// ==================== merged pack kernel ====================
// blocks: [0,1800) A1 per (bq,slab) | [1800,1930) B1 | [1930,5530) B2 | [5530,5600) fsnorm

#define NB_A1 (150 * NSLAB)
#define NB_B1 (10 * KP1)
#define NB_B2 (150 * KP2)

__global__ void pack_all(const float* __restrict__ fq, const float* __restrict__ fs) {
    __shared__ float buf[16 * 433];   // 6928 floats; A1 uses [208][33], B1 [16][385], B2 [196][17]
    int bid = blockIdx.x;
    if (bid < NB_A1) {
        // A1 slice: all 13 panels for (bq, slab). buf[t][d] = SCALE*Fq[t][d0+d], t in [0,208)
        int s  = bid % NSLAB;
        int bq = bid / NSLAB;
        const float* Fq = fq + (size_t)bq * T_ * C_;
        int d0 = s * DT;
        for (int idx = threadIdx.x; idx < 208 * 32; idx += 256) {
            int t = idx >> 5, d = idx & 31;
            buf[t * 33 + d] = (t < T_) ? SCALE * Fq[(size_t)t * C_ + d0 + d] : 0.f;
        }
        __syncthreads();
        u32* dst = g_A1 + (size_t)bid * KP1 * A1_PANEL;
        int idx = threadIdx.x;
        int T   = (idx >> 7) & 1;
        int lane = (idx >> 2) & 31;
        int reg  = idx & 3;
        int grr = lane >> 2, gcc = lane & 3;
        int dl = T * 16 + grr + ((reg & 1) ? 8 : 0);
        int klb = 2 * gcc + ((reg & 2) ? 8 : 0);
        for (int p = 0; p < KP1; p++) {
            int t = p * 16 + klb;
            dst[p * A1_PANEL + idx] = hpack(buf[t * 33 + dl], buf[(t + 1) * 33 + dl]);
        }
    } else if (bid < NB_A1 + NB_B1) {
        int b = bid - NB_A1;
        int p  = b % KP1;
        int bn = b / KP1;
        const float* Fs = fs + (size_t)bn * T_ * C_;
        for (int idx = threadIdx.x; idx < 16 * C_; idx += 256) {
            int k = idx / C_, c = idx % C_;
            int t = p * 16 + k;
            buf[k * 385 + c] = (t < T_) ? Fs[(size_t)t * C_ + c] : 0.f;
        }
        __syncthreads();
        u32* dst = g_B1 + (size_t)b * B1_PANEL;
        for (int idx = threadIdx.x; idx < B1_PANEL; idx += 256) {
            int G    = idx >> 6;
            int lane = (idx >> 1) & 31;
            int reg  = idx & 1;
            int grr = lane >> 2, gcc = lane & 3;
            int n  = G * 8 + grr;
            int kl = 2 * gcc + 8 * reg;
            dst[idx] = hpack(buf[kl * 385 + n], buf[(kl + 1) * 385 + n]);
        }
    } else if (bid < NB_A1 + NB_B1 + NB_B2) {
        int b = bid - NB_A1 - NB_B1;
        int p  = b % KP2;
        int bq = b / KP2;
        const float* Fq = fq + (size_t)bq * T_ * C_;
        for (int idx = threadIdx.x; idx < T_ * 16; idx += 256) {
            int t = idx >> 4, c = idx & 15;
            buf[t * 17 + c] = Fq[(size_t)t * C_ + p * 16 + c];
        }
        __syncthreads();
        u32* dst = g_B2 + (size_t)b * B2_PANEL;
        for (int idx = threadIdx.x; idx < B2_PANEL; idx += 256) {
            int G    = idx >> 6;
            int lane = (idx >> 1) & 31;
            int reg  = idx & 1;
            int grr = lane >> 2, gcc = lane & 3;
            int t  = G * 8 + grr;
            int kl = 2 * gcc + 8 * reg;
            float x0 = 0.f, x1 = 0.f;
            if (t < T_) { x0 = buf[t * 17 + kl]; x1 = buf[t * 17 + kl + 1]; }
            dst[idx] = hpack(x0, x1);
        }
    } else {
        int b = bid - NB_A1 - NB_B1 - NB_B2;
        int bn = b / 7;
        int base = (b % 7) * 28;
        int wid = threadIdx.x >> 5, lane = threadIdx.x & 31;
        const float* Fs = fs + (size_t)bn * T_ * C_;
        for (int r = base + wid; r < base + 28 && r < T_; r += 8) {
            float s = 0.f;
            #pragma unroll
            for (int u = 0; u < 12; u++) {
                float v = Fs[(size_t)r * C_ + lane + 32 * u];
                s += v * v;
            }
            #pragma unroll
            for (int o = 16; o > 0; o >>= 1) s += __shfl_xor_sync(0xffffffffu, s, o);
            if (lane == 0) g_nfs[bn * T_ + r] = sqrtf(s);
        }
    }
}

// ==================== main kernel ====================

__global__ __launch_bounds__(TPB, 2)
void episodic_main(const float* __restrict__ fs_g) {
    extern __shared__ u32 smu[];
    float* smf = (float*)smu;
    const u32 smbase = (u32)__cvta_generic_to_shared(smu);

    const int cid = blockIdx.x;
    const int bx = cid >> 1;
    const int half = cid & 1;
    const int nn = bx % N_;
    const int bq = bx / N_;
    const int bb = bq / Q_;
    const int bn = bb * N_ + nn;
    const float* __restrict__ Fs = fs_g + (size_t)bn * T_ * C_;

    const int tid = threadIdx.x;
    const int wid = tid >> 5, lane = tid & 31;
    const int gr = lane >> 2, gc = lane & 3;
    const int ng2 = (wid == 0) ? 4 : 3;
    const int g2base = (wid == 0) ? 0 : 4 + (wid - 1) * 3;

    for (int i = tid; i < NT2; i += TPB) { smf[U_PN + i] = 0.f; smf[U_PQ + i] = 0.f; }
    __syncthreads();

    const u32* gB1 = g_B1 + (size_t)bn * KP1 * B1_PANEL;
    const u32* gB2 = g_B2 + (size_t)bq * KP2 * B2_PANEL;

    for (int s = 0; s < HSLAB; s++) {
        const int slab = half * HSLAB + s;
        const int d0 = slab * DT;
        const u32* gA1 = g_A1 + (size_t)(bq * NSLAB + slab) * KP1 * A1_PANEL;

        // ---------------- GEMM1: 7 iterations of 2 panels ----------------
        float acc1[2][6][4];
        #pragma unroll
        for (int mt = 0; mt < 2; mt++)
            #pragma unroll
            for (int nt = 0; nt < 6; nt++)
                #pragma unroll
                for (int e = 0; e < 4; e++) acc1[mt][nt][e] = 0.f;

        {
            const float4* srcB = (const float4*)(gB1);
            u32 dstB = smbase + (U_B) * 4;
            for (int i = tid; i < 1536; i += TPB) cp16(dstB + i * 16, srcB + i);
            if (tid < 128) cp16(smbase + (U_A1) * 4 + tid * 16, ((const float4*)gA1) + tid);
            CP_COMMIT();
        }
        for (int it = 0; it < 7; it++) {
            const int buf = it & 1;
            CP_WAIT0();
            __syncthreads();
            if (it + 1 < 7) {
                int base = 2 * (it + 1);
                int npan_n = (base + 1 < KP1) ? 2 : 1;
                const float4* srcB = (const float4*)(gB1 + (size_t)base * B1_PANEL);
                u32 dstB = smbase + (U_B + (buf ^ 1) * U_BSZ) * 4;
                int n4 = npan_n * (B1_PANEL / 4);
                for (int i = tid; i < n4; i += TPB) cp16(dstB + i * 16, srcB + i);
                const float4* srcA = (const float4*)(gA1 + (size_t)base * A1_PANEL);
                int na = npan_n * (A1_PANEL / 4);
                if (tid < na)
                    cp16(smbase + (U_A1 + (buf ^ 1) * 2 * A1_PANEL) * 4 + tid * 16, srcA + tid);
                CP_COMMIT();
            }
            int npan = (2 * it + 1 < KP1) ? 2 : 1;
            for (int sub = 0; sub < npan; sub++) {
                const u32* bA = smu + U_A1 + buf * 2 * A1_PANEL + sub * A1_PANEL;
                const u32* bB = smu + U_B + buf * U_BSZ + sub * B1_PANEL;
                u32 ah[2][4];
                #pragma unroll
                for (int mt = 0; mt < 2; mt++) {
                    uint4 h = *(const uint4*)&bA[(mt * 32 + lane) * 4];
                    ah[mt][0] = h.x; ah[mt][1] = h.y; ah[mt][2] = h.z; ah[mt][3] = h.w;
                }
                #pragma unroll
                for (int np = 0; np < 3; np++) {
                    int G0 = wid * 6 + 2 * np;
                    uint2 b0 = *(const uint2*)&bB[(G0 * 32 + lane) * 2];
                    uint2 b1 = *(const uint2*)&bB[((G0 + 1) * 32 + lane) * 2];
                    #pragma unroll
                    for (int mt = 0; mt < 2; mt++) mma16(acc1[mt][2 * np],     ah[mt], b0.x, b0.y);
                    #pragma unroll
                    for (int mt = 0; mt < 2; mt++) mma16(acc1[mt][2 * np + 1], ah[mt], b1.x, b1.y);
                }
            }
        }

        // ---------------- softmax ----------------
        #pragma unroll
        for (int mt = 0; mt < 2; mt++)
            #pragma unroll
            for (int h = 0; h < 2; h++) {
                float mx = -INFINITY;
                #pragma unroll
                for (int nt = 0; nt < 6; nt++)
                    mx = fmaxf(mx, fmaxf(acc1[mt][nt][2 * h], acc1[mt][nt][2 * h + 1]));
                mx = fmaxf(mx, __shfl_xor_sync(0xffffffffu, mx, 1));
                mx = fmaxf(mx, __shfl_xor_sync(0xffffffffu, mx, 2));
                int row = mt * 16 + gr + 8 * h;
                if (gc == 0) smf[U_PMAX + row * 8 + wid] = mx;
            }
        __syncthreads();
        #pragma unroll
        for (int mt = 0; mt < 2; mt++)
            #pragma unroll
            for (int h = 0; h < 2; h++) {
                int row = mt * 16 + gr + 8 * h;
                float gmax = -INFINITY;
                #pragma unroll
                for (int w = 0; w < 8; w++)
                    gmax = fmaxf(gmax, smf[U_PMAX + row * 8 + w]);
                float s2 = 0.f;
                #pragma unroll
                for (int nt = 0; nt < 6; nt++) {
                    float v0 = __expf(acc1[mt][nt][2 * h] - gmax);
                    float v1 = __expf(acc1[mt][nt][2 * h + 1] - gmax);
                    acc1[mt][nt][2 * h] = v0;
                    acc1[mt][nt][2 * h + 1] = v1;
                    s2 += v0 + v1;
                }
                s2 += __shfl_xor_sync(0xffffffffu, s2, 1);
                s2 += __shfl_xor_sync(0xffffffffu, s2, 2);
                if (gc == 0) smf[U_PSUM + row * 8 + wid] = s2;
            }
        __syncthreads();
        if (wid == 0 && gc == 0) {
            #pragma unroll
            for (int mt = 0; mt < 2; mt++)
                #pragma unroll
                for (int h = 0; h < 2; h++) {
                    int row = mt * 16 + gr + 8 * h;
                    float tot = 0.f;
                    #pragma unroll
                    for (int w = 0; w < 8; w++) tot += smf[U_PSUM + row * 8 + w];
                    smf[U_RINV + row] = 1.0f / tot;
                }
        }

        // pack Pexp (fp16) into GEMM2 A-fragment layout
        #pragma unroll
        for (int mt = 0; mt < 2; mt++) {
            #pragma unroll
            for (int np = 0; np < 3; np++) {
                int G0 = wid * 6 + 2 * np;
                int p  = G0 >> 1;
                u32 vh0 = hpack(acc1[mt][2 * np][0], acc1[mt][2 * np][1]);
                u32 vh1 = hpack(acc1[mt][2 * np][2], acc1[mt][2 * np][3]);
                u32 vh2 = hpack(acc1[mt][2 * np + 1][0], acc1[mt][2 * np + 1][1]);
                u32 vh3 = hpack(acc1[mt][2 * np + 1][2], acc1[mt][2 * np + 1][3]);
                *(uint4*)&smu[U_A2 + ((p * 2 + mt) * 32 + lane) * 4] =
                    make_uint4(vh0, vh1, vh2, vh3);
            }
        }
        __syncthreads();

        // ---------------- GEMM2: 6 iterations of 4 panels ----------------
        float acc2[2][4][4];
        #pragma unroll
        for (int mt = 0; mt < 2; mt++)
            #pragma unroll
            for (int nt = 0; nt < 4; nt++)
                #pragma unroll
                for (int e = 0; e < 4; e++) acc2[mt][nt][e] = 0.f;

        {
            const float4* srcB = (const float4*)(gB2);
            u32 dstB = smbase + (U_B) * 4;
            for (int i = tid; i < 1600; i += TPB) cp16(dstB + i * 16, srcB + i);
            CP_COMMIT();
        }
        for (int it = 0; it < 6; it++) {
            const int buf = it & 1;
            CP_WAIT0();
            __syncthreads();
            if (it + 1 < 6) {
                const float4* srcB = (const float4*)(gB2 + (size_t)(4 * it + 4) * B2_PANEL);
                u32 dstB = smbase + (U_B + (buf ^ 1) * U_BSZ) * 4;
                for (int i = tid; i < 1600; i += TPB) cp16(dstB + i * 16, srcB + i);
                CP_COMMIT();
            }
            #pragma unroll
            for (int sub = 0; sub < 4; sub++) {
                int p = 4 * it + sub;
                const u32* bB = smu + U_B + buf * U_BSZ + sub * B2_PANEL;
                u32 ah[2][4];
                #pragma unroll
                for (int mt = 0; mt < 2; mt++) {
                    uint4 h = *(const uint4*)&smu[U_A2 + ((p * 2 + mt) * 32 + lane) * 4];
                    ah[mt][0] = h.x; ah[mt][1] = h.y; ah[mt][2] = h.z; ah[mt][3] = h.w;
                }
                for (int nt = 0; nt < ng2; nt++) {
                    int G = g2base + nt;
                    uint2 b2 = *(const uint2*)&bB[(G * 32 + lane) * 2];
                    #pragma unroll
                    for (int mt = 0; mt < 2; mt++) mma16(acc2[mt][nt], ah[mt], b2.x, b2.y);
                }
            }
        }
        __syncthreads();

        // ---------------- epilogue ----------------
        for (int nt = 0; nt < ng2; nt++) {
            int G = g2base + nt;
            int ta = G * 8 + 2 * gc;
            int tb = ta + 1;
            float pn_a = 0.f, pq_a = 0.f, pn_b = 0.f, pq_b = 0.f;
            #pragma unroll
            for (int mt = 0; mt < 2; mt++) {
                int rb1 = mt * 16 + gr;
                int rb2 = rb1 + 8;
                float r1 = smf[U_RINV + rb1];
                float r2 = smf[U_RINV + rb2];
                float v0 = acc2[mt][nt][0] * r1;
                float v1 = acc2[mt][nt][1] * r1;
                float v2 = acc2[mt][nt][2] * r2;
                float v3 = acc2[mt][nt][3] * r2;
                int gd1 = d0 + rb1, gd2 = d0 + rb2;
                float fa1 = 0.f, fa2 = 0.f, fb1 = 0.f, fb2 = 0.f;
                if (ta < T_) { fa1 = Fs[(size_t)ta * C_ + gd1]; fa2 = Fs[(size_t)ta * C_ + gd2]; }
                if (tb < T_) { fb1 = Fs[(size_t)tb * C_ + gd1]; fb2 = Fs[(size_t)tb * C_ + gd2]; }
                pn_a += v0 * fa1 + v2 * fa2;
                pq_a += v0 * v0 + v2 * v2;
                pn_b += v1 * fb1 + v3 * fb2;
                pq_b += v1 * v1 + v3 * v3;
            }
            #pragma unroll
            for (int o = 4; o <= 16; o <<= 1) {
                pn_a += __shfl_xor_sync(0xffffffffu, pn_a, o);
                pq_a += __shfl_xor_sync(0xffffffffu, pq_a, o);
                pn_b += __shfl_xor_sync(0xffffffffu, pn_b, o);
                pq_b += __shfl_xor_sync(0xffffffffu, pq_b, o);
            }
            if (lane < 4) {
                smf[U_PN + ta] += pn_a;
                smf[U_PQ + ta] += pq_a;
                smf[U_PN + tb] += pn_b;
                smf[U_PQ + tb] += pq_b;
            }
        }
        __syncthreads();
    }

    if (tid < NT2) {
        g_pn[(size_t)cid * NT2 + tid] = smf[U_PN + tid];
        g_pq[(size_t)cid * NT2 + tid] = smf[U_PQ + tid];
    }
}

// ==================== merged final kernel ====================

__global__ void final_kernel(const float* __restrict__ xq,
                             const float* __restrict__ xs,
                             float* __restrict__ out) {
    int gw = (blockIdx.x * blockDim.x + threadIdx.x) >> 5;
    int lane = threadIdx.x & 31;
    if (gw < B_ * Q_) {
        int bb = gw / Q_;
        float acc = 0.f;
        for (int n = 0; n < N_; n++) {
            int w = gw * N_ + n;
            int bn = bb * N_ + n;
            float local = -INFINITY;
            for (int t = lane; t < T_; t += 32) {
                float num = g_pn[(size_t)(2 * w) * NT2 + t] + g_pn[(size_t)(2 * w + 1) * NT2 + t];
                float nrm = g_pq[(size_t)(2 * w) * NT2 + t] + g_pq[(size_t)(2 * w + 1) * NT2 + t];
                float denom = fmaxf(sqrtf(nrm) * g_nfs[bn * T_ + t], 1e-8f);
                local = fmaxf(local, num / denom);
            }
            #pragma unroll
            for (int o = 16; o > 0; o >>= 1)
                local = fmaxf(local, __shfl_xor_sync(0xffffffffu, local, o));
            acc += local;
        }
        if (lane == 0) out[gw] = acc * (1.0f / N_);
    } else if (gw < B_ * Q_ + B_ * Q_ * N_) {
        int w = gw - B_ * Q_;
        int nn = w % N_;
        int qq = (w / N_) % Q_;
        int bb = w / (N_ * Q_);
        const float* q = xq + (size_t)(bb * Q_ + qq) * D_;
        const float* s = xs + (size_t)(bb * N_ + nn) * D_;
        float dot = 0.f, nq = 0.f, ns = 0.f;
        #pragma unroll
        for (int u = 0; u < D_ / 32; u++) {
            float a = q[lane + 32 * u];
            float b = s[lane + 32 * u];
            dot += a * b;
            nq += a * a;
            ns += b * b;
        }
        #pragma unroll
        for (int o = 16; o > 0; o >>= 1) {
            dot += __shfl_xor_sync(0xffffffffu, dot, o);
            nq  += __shfl_xor_sync(0xffffffffu, nq, o);
            ns  += __shfl_xor_sync(0xffffffffu, ns, o);
        }
        if (lane == 0) {
            float den = fmaxf(sqrtf(nq), 1e-12f) * fmaxf(sqrtf(ns), 1e-12f);
            out[B_ * Q_ + w] = 10.0f * dot / den;
        }
    }
}

extern "C" void kernel_launch(void* const* d_in, const int* in_sizes, int n_in,
                              void* d_out, int out_size) {
    const float* fq = (const float*)d_in[0];
    const float* fs = (const float*)d_in[1];
    const float* xq = (const float*)d_in[2];
    const float* xs = (const float*)d_in[3];
    float* out = (float*)d_out;

    pack_all<<<NB_A1 + NB_B1 + NB_B2 + 70, 256>>>(fq, fs);

    const size_t smem_bytes = (size_t)U_TOT * sizeof(u32);
    cudaFuncSetAttribute(episodic_main,
                         cudaFuncAttributeMaxDynamicSharedMemorySize,
                         (int)smem_bytes);
    episodic_main<<<1500, TPB, smem_bytes>>>(fs);

    final_kernel<<<(900 * 32 + 255) / 256, 256>>>(xq, xs, out);
}

// round 16
// speedup vs baseline: 1.9863x; 1.0220x over previous
#include <cuda_runtime.h>
#include <cuda_fp16.h>
#include <math.h>
#include <stdint.h>

typedef unsigned int u32;

#define B_ 2
#define Q_ 75
#define N_ 5
#define T_ 196
#define C_ 384
#define D_ 384
#define SCALE (1.0f / 14.0f)

#define TPB 256
#define DT 32
#define NSLAB 12
#define HSLAB 6
#define KP1 13
#define KP2 24
#define NT2 200

#define A1_PANEL 256     // [T2][lane32][reg4] fp16x2
#define B1_PANEL 3072    // [Gpair24][lane32][Ge.r0,Ge.r1,Go.r0,Go.r1] fp16x2
#define B2_PANEL 1600    // [G25][lane32][reg2] fp16x2
#define U_BSZ 6400       // staging buffer region (max(2*B1P, 4*B2P))

__device__ u32 g_A1[150 * NSLAB * KP1 * A1_PANEL];
__device__ u32 g_B1[10 * KP1 * B1_PANEL];
__device__ u32 g_B2[150 * KP2 * B2_PANEL];
__device__ float g_pn[1500 * NT2];
__device__ float g_pq[1500 * NT2];
__device__ float g_nfs[10 * T_];

// smem layout (u32 offsets)
#define U_A2   0                         // [p24][mt2][lane32][r4] = 6144
#define U_B    6144                      // dbuf 2 x U_BSZ = 12800
#define U_A1   (U_B + 2 * U_BSZ)         // 18944: dbuf 2 x 512
#define U_PN   (U_A1 + 4 * A1_PANEL)     // 19968
#define U_PQ   (U_PN + NT2)
#define U_RINV (U_PQ + NT2)
#define U_PMAX (U_RINV + 32)
#define U_PSUM (U_PMAX + 256)
#define U_TOT  (U_PSUM + 256)            // 20912 u32 = 83648 B

__device__ __forceinline__ u32 hpack(float x0, float x1) {
    __half2 h; h.x = __float2half_rn(x0); h.y = __float2half_rn(x1);
    return *(u32*)&h;
}

__device__ __forceinline__ void mma16(float* c, const u32* a, u32 b0, u32 b1) {
    asm volatile(
        "mma.sync.aligned.m16n8k16.row.col.f32.f16.f16.f32 "
        "{%0,%1,%2,%3},{%4,%5,%6,%7},{%8,%9},{%0,%1,%2,%3};"
        : "+f"(c[0]), "+f"(c[1]), "+f"(c[2]), "+f"(c[3])
        : "r"(a[0]), "r"(a[1]), "r"(a[2]), "r"(a[3]), "r"(b0), "r"(b1));
}

__device__ __forceinline__ void cp16(u32 daddr, const void* src) {
    asm volatile("cp.async.cg.shared.global [%0], [%1], 16;" :: "r"(daddr), "l"(src));
}
#define CP_COMMIT() asm volatile("cp.async.commit_group;" ::: "memory")
#define CP_WAIT0()  asm volatile("cp.async.wait_group 0;" ::: "memory")

// ==================== merged pack kernel ====================
// blocks: [0,1800) A1 per (bq,slab) | [1800,1930) B1 | [1930,3730) B2 pairs | [3730,3800) fsnorm

#define NB_A1 (150 * NSLAB)
#define NB_B1 (10 * KP1)
#define NB_B2 (150 * 12)

__global__ void pack_all(const float* __restrict__ fq, const float* __restrict__ fs) {
    __shared__ float buf[16 * 433];   // A1 [208][33], B1 [16][385], B2 [196][33]
    int bid = blockIdx.x;
    if (bid < NB_A1) {
        // A1 slice: all 13 panels for (bq, slab)
        int s  = bid % NSLAB;
        int bq = bid / NSLAB;
        const float* Fq = fq + (size_t)bq * T_ * C_;
        int d0 = s * DT;
        for (int idx = threadIdx.x; idx < 208 * 32; idx += 256) {
            int t = idx >> 5, d = idx & 31;
            buf[t * 33 + d] = (t < T_) ? SCALE * Fq[(size_t)t * C_ + d0 + d] : 0.f;
        }
        __syncthreads();
        u32* dst = g_A1 + (size_t)bid * KP1 * A1_PANEL;
        int idx = threadIdx.x;
        int T   = (idx >> 7) & 1;
        int lane = (idx >> 2) & 31;
        int reg  = idx & 3;
        int grr = lane >> 2, gcc = lane & 3;
        int dl = T * 16 + grr + ((reg & 1) ? 8 : 0);
        int klb = 2 * gcc + ((reg & 2) ? 8 : 0);
        for (int p = 0; p < KP1; p++) {
            int t = p * 16 + klb;
            dst[p * A1_PANEL + idx] = hpack(buf[t * 33 + dl], buf[(t + 1) * 33 + dl]);
        }
    } else if (bid < NB_A1 + NB_B1) {
        // B1 panel, pair-interleaved fragment layout
        int b = bid - NB_A1;
        int p  = b % KP1;
        int bn = b / KP1;
        const float* Fs = fs + (size_t)bn * T_ * C_;
        for (int idx = threadIdx.x; idx < 16 * C_; idx += 256) {
            int k = idx / C_, c = idx % C_;
            int t = p * 16 + k;
            buf[k * 385 + c] = (t < T_) ? Fs[(size_t)t * C_ + c] : 0.f;
        }
        __syncthreads();
        u32* dst = g_B1 + (size_t)b * B1_PANEL;
        for (int idx = threadIdx.x; idx < B1_PANEL; idx += 256) {
            int pair = idx >> 7;
            int lane = (idx >> 2) & 31;
            int G    = pair * 2 + ((idx >> 1) & 1);
            int reg  = idx & 1;
            int grr = lane >> 2, gcc = lane & 3;
            int n  = G * 8 + grr;
            int kl = 2 * gcc + 8 * reg;
            dst[idx] = hpack(buf[kl * 385 + n], buf[(kl + 1) * 385 + n]);
        }
    } else if (bid < NB_A1 + NB_B1 + NB_B2) {
        // B2: 2 panels per block (32 c columns)
        int b  = bid - NB_A1 - NB_B1;
        int pp = b % 12;
        int bq = b / 12;
        const float* Fq = fq + (size_t)bq * T_ * C_;
        int c0 = pp * 32;
        for (int idx = threadIdx.x; idx < T_ * 32; idx += 256) {
            int t = idx >> 5, c = idx & 31;
            buf[t * 33 + c] = Fq[(size_t)t * C_ + c0 + c];
        }
        __syncthreads();
        u32* dst = g_B2 + (size_t)(bq * KP2 + pp * 2) * B2_PANEL;
        for (int idx = threadIdx.x; idx < 2 * B2_PANEL; idx += 256) {
            int pl   = idx / B2_PANEL;          // panel within pair
            int rem  = idx % B2_PANEL;
            int G    = rem >> 6;
            int lane = (rem >> 1) & 31;
            int reg  = rem & 1;
            int grr = lane >> 2, gcc = lane & 3;
            int t  = G * 8 + grr;
            int kl = pl * 16 + 2 * gcc + 8 * reg;
            float x0 = 0.f, x1 = 0.f;
            if (t < T_) { x0 = buf[t * 33 + kl]; x1 = buf[t * 33 + kl + 1]; }
            dst[(size_t)pl * B2_PANEL + rem] = hpack(x0, x1);
        }
    } else {
        int b = bid - NB_A1 - NB_B1 - NB_B2;
        int bn = b / 7;
        int base = (b % 7) * 28;
        int wid = threadIdx.x >> 5, lane = threadIdx.x & 31;
        const float* Fs = fs + (size_t)bn * T_ * C_;
        for (int r = base + wid; r < base + 28 && r < T_; r += 8) {
            float s = 0.f;
            #pragma unroll
            for (int u = 0; u < 12; u++) {
                float v = Fs[(size_t)r * C_ + lane + 32 * u];
                s += v * v;
            }
            #pragma unroll
            for (int o = 16; o > 0; o >>= 1) s += __shfl_xor_sync(0xffffffffu, s, o);
            if (lane == 0) g_nfs[bn * T_ + r] = sqrtf(s);
        }
    }
}

// ==================== main kernel ====================

__global__ __launch_bounds__(TPB, 2)
void episodic_main(const float* __restrict__ fs_g) {
    extern __shared__ u32 smu[];
    float* smf = (float*)smu;
    const u32 smbase = (u32)__cvta_generic_to_shared(smu);

    const int cid = blockIdx.x;
    const int bx = cid >> 1;
    const int half = cid & 1;
    const int nn = bx % N_;
    const int bq = bx / N_;
    const int bb = bq / Q_;
    const int bn = bb * N_ + nn;
    const float* __restrict__ Fs = fs_g + (size_t)bn * T_ * C_;

    const int tid = threadIdx.x;
    const int wid = tid >> 5, lane = tid & 31;
    const int gr = lane >> 2, gc = lane & 3;
    const int ng2 = (wid == 0) ? 4 : 3;
    const int g2base = (wid == 0) ? 0 : 4 + (wid - 1) * 3;

    for (int i = tid; i < NT2; i += TPB) { smf[U_PN + i] = 0.f; smf[U_PQ + i] = 0.f; }
    __syncthreads();

    const u32* gB1 = g_B1 + (size_t)bn * KP1 * B1_PANEL;
    const u32* gB2 = g_B2 + (size_t)bq * KP2 * B2_PANEL;

    for (int s = 0; s < HSLAB; s++) {
        const int slab = half * HSLAB + s;
        const int d0 = slab * DT;
        const u32* gA1 = g_A1 + (size_t)(bq * NSLAB + slab) * KP1 * A1_PANEL;

        // ---------------- GEMM1: 7 iterations of 2 panels ----------------
        float acc1[2][6][4];
        #pragma unroll
        for (int mt = 0; mt < 2; mt++)
            #pragma unroll
            for (int nt = 0; nt < 6; nt++)
                #pragma unroll
                for (int e = 0; e < 4; e++) acc1[mt][nt][e] = 0.f;

        {
            const float4* srcB = (const float4*)(gB1);
            u32 dstB = smbase + (U_B) * 4;
            for (int i = tid; i < 1536; i += TPB) cp16(dstB + i * 16, srcB + i);
            if (tid < 128) cp16(smbase + (U_A1) * 4 + tid * 16, ((const float4*)gA1) + tid);
            CP_COMMIT();
        }
        for (int it = 0; it < 7; it++) {
            const int buf = it & 1;
            CP_WAIT0();
            __syncthreads();
            if (it + 1 < 7) {
                int base = 2 * (it + 1);
                int npan_n = (base + 1 < KP1) ? 2 : 1;
                const float4* srcB = (const float4*)(gB1 + (size_t)base * B1_PANEL);
                u32 dstB = smbase + (U_B + (buf ^ 1) * U_BSZ) * 4;
                int n4 = npan_n * (B1_PANEL / 4);
                for (int i = tid; i < n4; i += TPB) cp16(dstB + i * 16, srcB + i);
                const float4* srcA = (const float4*)(gA1 + (size_t)base * A1_PANEL);
                int na = npan_n * (A1_PANEL / 4);
                if (tid < na)
                    cp16(smbase + (U_A1 + (buf ^ 1) * 2 * A1_PANEL) * 4 + tid * 16, srcA + tid);
                CP_COMMIT();
            }
            int npan = (2 * it + 1 < KP1) ? 2 : 1;
            for (int sub = 0; sub < npan; sub++) {
                const u32* bA = smu + U_A1 + buf * 2 * A1_PANEL + sub * A1_PANEL;
                const u32* bB = smu + U_B + buf * U_BSZ + sub * B1_PANEL;
                u32 ah[2][4];
                #pragma unroll
                for (int mt = 0; mt < 2; mt++) {
                    uint4 h = *(const uint4*)&bA[(mt * 32 + lane) * 4];
                    ah[mt][0] = h.x; ah[mt][1] = h.y; ah[mt][2] = h.z; ah[mt][3] = h.w;
                }
                #pragma unroll
                for (int np = 0; np < 3; np++) {
                    int pairIdx = wid * 3 + np;
                    uint4 b4 = *(const uint4*)&bB[(pairIdx * 32 + lane) * 4];
                    #pragma unroll
                    for (int mt = 0; mt < 2; mt++) mma16(acc1[mt][2 * np],     ah[mt], b4.x, b4.y);
                    #pragma unroll
                    for (int mt = 0; mt < 2; mt++) mma16(acc1[mt][2 * np + 1], ah[mt], b4.z, b4.w);
                }
            }
        }

        // ---------------- softmax ----------------
        #pragma unroll
        for (int mt = 0; mt < 2; mt++)
            #pragma unroll
            for (int h = 0; h < 2; h++) {
                float mx = -INFINITY;
                #pragma unroll
                for (int nt = 0; nt < 6; nt++)
                    mx = fmaxf(mx, fmaxf(acc1[mt][nt][2 * h], acc1[mt][nt][2 * h + 1]));
                mx = fmaxf(mx, __shfl_xor_sync(0xffffffffu, mx, 1));
                mx = fmaxf(mx, __shfl_xor_sync(0xffffffffu, mx, 2));
                int row = mt * 16 + gr + 8 * h;
                if (gc == 0) smf[U_PMAX + row * 8 + wid] = mx;
            }
        __syncthreads();
        #pragma unroll
        for (int mt = 0; mt < 2; mt++)
            #pragma unroll
            for (int h = 0; h < 2; h++) {
                int row = mt * 16 + gr + 8 * h;
                float gmax = -INFINITY;
                #pragma unroll
                for (int w = 0; w < 8; w++)
                    gmax = fmaxf(gmax, smf[U_PMAX + row * 8 + w]);
                float s2 = 0.f;
                #pragma unroll
                for (int nt = 0; nt < 6; nt++) {
                    float v0 = __expf(acc1[mt][nt][2 * h] - gmax);
                    float v1 = __expf(acc1[mt][nt][2 * h + 1] - gmax);
                    acc1[mt][nt][2 * h] = v0;
                    acc1[mt][nt][2 * h + 1] = v1;
                    s2 += v0 + v1;
                }
                s2 += __shfl_xor_sync(0xffffffffu, s2, 1);
                s2 += __shfl_xor_sync(0xffffffffu, s2, 2);
                if (gc == 0) smf[U_PSUM + row * 8 + wid] = s2;
            }
        __syncthreads();
        if (wid == 0 && gc == 0) {
            #pragma unroll
            for (int mt = 0; mt < 2; mt++)
                #pragma unroll
                for (int h = 0; h < 2; h++) {
                    int row = mt * 16 + gr + 8 * h;
                    float tot = 0.f;
                    #pragma unroll
                    for (int w = 0; w < 8; w++) tot += smf[U_PSUM + row * 8 + w];
                    smf[U_RINV + row] = 1.0f / tot;
                }
        }

        // pack Pexp (fp16) into GEMM2 A-fragment layout
        #pragma unroll
        for (int mt = 0; mt < 2; mt++) {
            #pragma unroll
            for (int np = 0; np < 3; np++) {
                int p = wid * 3 + np;
                u32 vh0 = hpack(acc1[mt][2 * np][0], acc1[mt][2 * np][1]);
                u32 vh1 = hpack(acc1[mt][2 * np][2], acc1[mt][2 * np][3]);
                u32 vh2 = hpack(acc1[mt][2 * np + 1][0], acc1[mt][2 * np + 1][1]);
                u32 vh3 = hpack(acc1[mt][2 * np + 1][2], acc1[mt][2 * np + 1][3]);
                *(uint4*)&smu[U_A2 + ((p * 2 + mt) * 32 + lane) * 4] =
                    make_uint4(vh0, vh1, vh2, vh3);
            }
        }
        __syncthreads();

        // ---------------- GEMM2: 6 iterations of 4 panels ----------------
        float acc2[2][4][4];
        #pragma unroll
        for (int mt = 0; mt < 2; mt++)
            #pragma unroll
            for (int nt = 0; nt < 4; nt++)
                #pragma unroll
                for (int e = 0; e < 4; e++) acc2[mt][nt][e] = 0.f;

        {
            const float4* srcB = (const float4*)(gB2);
            u32 dstB = smbase + (U_B) * 4;
            for (int i = tid; i < 1600; i += TPB) cp16(dstB + i * 16, srcB + i);
            CP_COMMIT();
        }
        for (int it = 0; it < 6; it++) {
            const int buf = it & 1;
            CP_WAIT0();
            __syncthreads();
            if (it + 1 < 6) {
                const float4* srcB = (const float4*)(gB2 + (size_t)(4 * it + 4) * B2_PANEL);
                u32 dstB = smbase + (U_B + (buf ^ 1) * U_BSZ) * 4;
                for (int i = tid; i < 1600; i += TPB) cp16(dstB + i * 16, srcB + i);
                CP_COMMIT();
            }
            #pragma unroll
            for (int sub = 0; sub < 4; sub++) {
                int p = 4 * it + sub;
                const u32* bB = smu + U_B + buf * U_BSZ + sub * B2_PANEL;
                u32 ah[2][4];
                #pragma unroll
                for (int mt = 0; mt < 2; mt++) {
                    uint4 h = *(const uint4*)&smu[U_A2 + ((p * 2 + mt) * 32 + lane) * 4];
                    ah[mt][0] = h.x; ah[mt][1] = h.y; ah[mt][2] = h.z; ah[mt][3] = h.w;
                }
                for (int nt = 0; nt < ng2; nt++) {
                    int G = g2base + nt;
                    uint2 b2 = *(const uint2*)&bB[(G * 32 + lane) * 2];
                    #pragma unroll
                    for (int mt = 0; mt < 2; mt++) mma16(acc2[mt][nt], ah[mt], b2.x, b2.y);
                }
            }
        }
        __syncthreads();

        // ---------------- epilogue ----------------
        for (int nt = 0; nt < ng2; nt++) {
            int G = g2base + nt;
            int ta = G * 8 + 2 * gc;
            int tb = ta + 1;
            float pn_a = 0.f, pq_a = 0.f, pn_b = 0.f, pq_b = 0.f;
            #pragma unroll
            for (int mt = 0; mt < 2; mt++) {
                int rb1 = mt * 16 + gr;
                int rb2 = rb1 + 8;
                float r1 = smf[U_RINV + rb1];
                float r2 = smf[U_RINV + rb2];
                float v0 = acc2[mt][nt][0] * r1;
                float v1 = acc2[mt][nt][1] * r1;
                float v2 = acc2[mt][nt][2] * r2;
                float v3 = acc2[mt][nt][3] * r2;
                int gd1 = d0 + rb1, gd2 = d0 + rb2;
                float fa1 = 0.f, fa2 = 0.f, fb1 = 0.f, fb2 = 0.f;
                if (ta < T_) { fa1 = Fs[(size_t)ta * C_ + gd1]; fa2 = Fs[(size_t)ta * C_ + gd2]; }
                if (tb < T_) { fb1 = Fs[(size_t)tb * C_ + gd1]; fb2 = Fs[(size_t)tb * C_ + gd2]; }
                pn_a += v0 * fa1 + v2 * fa2;
                pq_a += v0 * v0 + v2 * v2;
                pn_b += v1 * fb1 + v3 * fb2;
                pq_b += v1 * v1 + v3 * v3;
            }
            #pragma unroll
            for (int o = 4; o <= 16; o <<= 1) {
                pn_a += __shfl_xor_sync(0xffffffffu, pn_a, o);
                pq_a += __shfl_xor_sync(0xffffffffu, pq_a, o);
                pn_b += __shfl_xor_sync(0xffffffffu, pn_b, o);
                pq_b += __shfl_xor_sync(0xffffffffu, pq_b, o);
            }
            if (lane < 4) {
                smf[U_PN + ta] += pn_a;
                smf[U_PQ + ta] += pq_a;
                smf[U_PN + tb] += pn_b;
                smf[U_PQ + tb] += pq_b;
            }
        }
        __syncthreads();
    }

    if (tid < NT2) {
        g_pn[(size_t)cid * NT2 + tid] = smf[U_PN + tid];
        g_pq[(size_t)cid * NT2 + tid] = smf[U_PQ + tid];
    }
}

// ==================== merged final kernel ====================

__global__ void final_kernel(const float* __restrict__ xq,
                             const float* __restrict__ xs,
                             float* __restrict__ out) {
    int gw = (blockIdx.x * blockDim.x + threadIdx.x) >> 5;
    int lane = threadIdx.x & 31;
    if (gw < B_ * Q_) {
        int bb = gw / Q_;
        float acc = 0.f;
        for (int n = 0; n < N_; n++) {
            int w = gw * N_ + n;
            int bn = bb * N_ + n;
            float local = -INFINITY;
            for (int t = lane; t < T_; t += 32) {
                float num = g_pn[(size_t)(2 * w) * NT2 + t] + g_pn[(size_t)(2 * w + 1) * NT2 + t];
                float nrm = g_pq[(size_t)(2 * w) * NT2 + t] + g_pq[(size_t)(2 * w + 1) * NT2 + t];
                float denom = fmaxf(sqrtf(nrm) * g_nfs[bn * T_ + t], 1e-8f);
                local = fmaxf(local, num / denom);
            }
            #pragma unroll
            for (int o = 16; o > 0; o >>= 1)
                local = fmaxf(local, __shfl_xor_sync(0xffffffffu, local, o));
            acc += local;
        }
        if (lane == 0) out[gw] = acc * (1.0f / N_);
    } else if (gw < B_ * Q_ + B_ * Q_ * N_) {
        int w = gw - B_ * Q_;
        int nn = w % N_;
        int qq = (w / N_) % Q_;
        int bb = w / (N_ * Q_);
        const float* q = xq + (size_t)(bb * Q_ + qq) * D_;
        const float* s = xs + (size_t)(bb * N_ + nn) * D_;
        float dot = 0.f, nq = 0.f, ns = 0.f;
        #pragma unroll
        for (int u = 0; u < D_ / 32; u++) {
            float a = q[lane + 32 * u];
            float b = s[lane + 32 * u];
            dot += a * b;
            nq += a * a;
            ns += b * b;
        }
        #pragma unroll
        for (int o = 16; o > 0; o >>= 1) {
            dot += __shfl_xor_sync(0xffffffffu, dot, o);
            nq  += __shfl_xor_sync(0xffffffffu, nq, o);
            ns  += __shfl_xor_sync(0xffffffffu, ns, o);
        }
        if (lane == 0) {
            float den = fmaxf(sqrtf(nq), 1e-12f) * fmaxf(sqrtf(ns), 1e-12f);
            out[B_ * Q_ + w] = 10.0f * dot / den;
        }
    }
}

extern "C" void kernel_launch(void* const* d_in, const int* in_sizes, int n_in,
                              void* d_out, int out_size) {
    const float* fq = (const float*)d_in[0];
    const float* fs = (const float*)d_in[1];
    const float* xq = (const float*)d_in[2];
    const float* xs = (const float*)d_in[3];
    float* out = (float*)d_out;

    pack_all<<<NB_A1 + NB_B1 + NB_B2 + 70, 256>>>(fq, fs);

    const size_t smem_bytes = (size_t)U_TOT * sizeof(u32);
    cudaFuncSetAttribute(episodic_main,
                         cudaFuncAttributeMaxDynamicSharedMemorySize,
                         (int)smem_bytes);
    episodic_main<<<1500, TPB, smem_bytes>>>(fs);

    final_kernel<<<(900 * 32 + 255) / 256, 256>>>(xq, xs, out);
}

// round 17
// speedup vs baseline: 2.0817x; 1.0480x over previous
#include <cuda_runtime.h>
#include <cuda_fp16.h>
#include <math.h>
#include <stdint.h>

typedef unsigned int u32;

#define B_ 2
#define Q_ 75
#define N_ 5
#define T_ 196
#define C_ 384
#define D_ 384
#define SCALE (1.0f / 14.0f)

#define TPB 256
#define DT 32
#define NSLAB 12
#define HSLAB 6
#define KP1 13
#define KP2 24
#define NT2 200

#define A1_PANEL 256     // [T2][lane32][reg4] fp16x2
#define B1_PANEL 3072    // [Gpair24][lane32][Ge.r0,Ge.r1,Go.r0,Go.r1] fp16x2
#define B2_PANEL 1600    // [G25][lane32][reg2] fp16x2

__device__ u32 g_A1[150 * NSLAB * KP1 * A1_PANEL];
__device__ u32 g_B1[10 * KP1 * B1_PANEL];
__device__ u32 g_B2[150 * KP2 * B2_PANEL];
__device__ float g_pn[1500 * NT2];
__device__ float g_pq[1500 * NT2];
__device__ float g_nfs[10 * T_];

// smem layout (u32 offsets) — U_B region is ALIASED:
//   GEMM1 phase: staging dbuf [2][6144] at U_B
//   repack/GEMM2 phase: A2 frags [6144] at U_B, GEMM2 staging dbuf [2][3200] at U_B+6144
#define U_B    0
#define U_A2   U_B                       // alias: valid only after GEMM1 of the slab
#define U_B2S  (U_B + 6144)              // GEMM2 staging base
#define U_A1   12544                     // dbuf 2 x 512
#define U_PN   (U_A1 + 4 * A1_PANEL)     // 13568
#define U_PQ   (U_PN + NT2)              // 13768
#define U_RINV (U_PQ + NT2)              // 13968
#define U_PMAX (U_RINV + 32)             // 14000
#define U_PSUM (U_PMAX + 256)            // 14256
#define U_TOT  (U_PSUM + 256)            // 14512 u32 = 58048 B (3 CTAs = 174 KB)

__device__ __forceinline__ u32 hpack(float x0, float x1) {
    __half2 h; h.x = __float2half_rn(x0); h.y = __float2half_rn(x1);
    return *(u32*)&h;
}

__device__ __forceinline__ void mma16(float* c, const u32* a, u32 b0, u32 b1) {
    asm volatile(
        "mma.sync.aligned.m16n8k16.row.col.f32.f16.f16.f32 "
        "{%0,%1,%2,%3},{%4,%5,%6,%7},{%8,%9},{%0,%1,%2,%3};"
        : "+f"(c[0]), "+f"(c[1]), "+f"(c[2]), "+f"(c[3])
        : "r"(a[0]), "r"(a[1]), "r"(a[2]), "r"(a[3]), "r"(b0), "r"(b1));
}

__device__ __forceinline__ void cp16(u32 daddr, const void* src) {
    asm volatile("cp.async.cg.shared.global [%0], [%1], 16;" :: "r"(daddr), "l"(src));
}
#define CP_COMMIT() asm volatile("cp.async.commit_group;" ::: "memory")
#define CP_WAIT0()  asm volatile("cp.async.wait_group 0;" ::: "memory")

// ==================== merged pack kernel ====================

#define NB_A1 (150 * NSLAB)
#define NB_B1 (10 * KP1)
#define NB_B2 (150 * 12)

__global__ void pack_all(const float* __restrict__ fq, const float* __restrict__ fs) {
    __shared__ float buf[16 * 433];
    int bid = blockIdx.x;
    if (bid < NB_A1) {
        int s  = bid % NSLAB;
        int bq = bid / NSLAB;
        const float* Fq = fq + (size_t)bq * T_ * C_;
        int d0 = s * DT;
        for (int idx = threadIdx.x; idx < 208 * 32; idx += 256) {
            int t = idx >> 5, d = idx & 31;
            buf[t * 33 + d] = (t < T_) ? SCALE * Fq[(size_t)t * C_ + d0 + d] : 0.f;
        }
        __syncthreads();
        u32* dst = g_A1 + (size_t)bid * KP1 * A1_PANEL;
        int idx = threadIdx.x;
        int T   = (idx >> 7) & 1;
        int lane = (idx >> 2) & 31;
        int reg  = idx & 3;
        int grr = lane >> 2, gcc = lane & 3;
        int dl = T * 16 + grr + ((reg & 1) ? 8 : 0);
        int klb = 2 * gcc + ((reg & 2) ? 8 : 0);
        for (int p = 0; p < KP1; p++) {
            int t = p * 16 + klb;
            dst[p * A1_PANEL + idx] = hpack(buf[t * 33 + dl], buf[(t + 1) * 33 + dl]);
        }
    } else if (bid < NB_A1 + NB_B1) {
        int b = bid - NB_A1;
        int p  = b % KP1;
        int bn = b / KP1;
        const float* Fs = fs + (size_t)bn * T_ * C_;
        for (int idx = threadIdx.x; idx < 16 * C_; idx += 256) {
            int k = idx / C_, c = idx % C_;
            int t = p * 16 + k;
            buf[k * 385 + c] = (t < T_) ? Fs[(size_t)t * C_ + c] : 0.f;
        }
        __syncthreads();
        u32* dst = g_B1 + (size_t)b * B1_PANEL;
        for (int idx = threadIdx.x; idx < B1_PANEL; idx += 256) {
            int pair = idx >> 7;
            int lane = (idx >> 2) & 31;
            int G    = pair * 2 + ((idx >> 1) & 1);
            int reg  = idx & 1;
            int grr = lane >> 2, gcc = lane & 3;
            int n  = G * 8 + grr;
            int kl = 2 * gcc + 8 * reg;
            dst[idx] = hpack(buf[kl * 385 + n], buf[(kl + 1) * 385 + n]);
        }
    } else if (bid < NB_A1 + NB_B1 + NB_B2) {
        int b  = bid - NB_A1 - NB_B1;
        int pp = b % 12;
        int bq = b / 12;
        const float* Fq = fq + (size_t)bq * T_ * C_;
        int c0 = pp * 32;
        for (int idx = threadIdx.x; idx < T_ * 32; idx += 256) {
            int t = idx >> 5, c = idx & 31;
            buf[t * 33 + c] = Fq[(size_t)t * C_ + c0 + c];
        }
        __syncthreads();
        u32* dst = g_B2 + (size_t)(bq * KP2 + pp * 2) * B2_PANEL;
        for (int idx = threadIdx.x; idx < 2 * B2_PANEL; idx += 256) {
            int pl   = idx / B2_PANEL;
            int rem  = idx % B2_PANEL;
            int G    = rem >> 6;
            int lane = (rem >> 1) & 31;
            int reg  = rem & 1;
            int grr = lane >> 2, gcc = lane & 3;
            int t  = G * 8 + grr;
            int kl = pl * 16 + 2 * gcc + 8 * reg;
            float x0 = 0.f, x1 = 0.f;
            if (t < T_) { x0 = buf[t * 33 + kl]; x1 = buf[t * 33 + kl + 1]; }
            dst[(size_t)pl * B2_PANEL + rem] = hpack(x0, x1);
        }
    } else {
        int b = bid - NB_A1 - NB_B1 - NB_B2;
        int bn = b / 7;
        int base = (b % 7) * 28;
        int wid = threadIdx.x >> 5, lane = threadIdx.x & 31;
        const float* Fs = fs + (size_t)bn * T_ * C_;
        for (int r = base + wid; r < base + 28 && r < T_; r += 8) {
            float s = 0.f;
            #pragma unroll
            for (int u = 0; u < 12; u++) {
                float v = Fs[(size_t)r * C_ + lane + 32 * u];
                s += v * v;
            }
            #pragma unroll
            for (int o = 16; o > 0; o >>= 1) s += __shfl_xor_sync(0xffffffffu, s, o);
            if (lane == 0) g_nfs[bn * T_ + r] = sqrtf(s);
        }
    }
}

// ==================== main kernel ====================

__global__ __launch_bounds__(TPB, 3)
void episodic_main(const float* __restrict__ fs_g) {
    extern __shared__ u32 smu[];
    float* smf = (float*)smu;
    const u32 smbase = (u32)__cvta_generic_to_shared(smu);

    const int cid = blockIdx.x;
    const int bx = cid >> 1;
    const int half = cid & 1;
    const int nn = bx % N_;
    const int bq = bx / N_;
    const int bb = bq / Q_;
    const int bn = bb * N_ + nn;
    const float* __restrict__ Fs = fs_g + (size_t)bn * T_ * C_;

    const int tid = threadIdx.x;
    const int wid = tid >> 5, lane = tid & 31;
    const int gr = lane >> 2, gc = lane & 3;
    const int ng2 = (wid == 0) ? 4 : 3;
    const int g2base = (wid == 0) ? 0 : 4 + (wid - 1) * 3;

    for (int i = tid; i < NT2; i += TPB) { smf[U_PN + i] = 0.f; smf[U_PQ + i] = 0.f; }
    __syncthreads();

    const u32* gB1 = g_B1 + (size_t)bn * KP1 * B1_PANEL;
    const u32* gB2 = g_B2 + (size_t)bq * KP2 * B2_PANEL;

    for (int s = 0; s < HSLAB; s++) {
        const int slab = half * HSLAB + s;
        const int d0 = slab * DT;
        const u32* gA1 = g_A1 + (size_t)(bq * NSLAB + slab) * KP1 * A1_PANEL;

        // ---------------- GEMM1: 7 iterations of 2 panels ----------------
        float acc1[2][6][4];
        #pragma unroll
        for (int mt = 0; mt < 2; mt++)
            #pragma unroll
            for (int nt = 0; nt < 6; nt++)
                #pragma unroll
                for (int e = 0; e < 4; e++) acc1[mt][nt][e] = 0.f;

        {
            const float4* srcB = (const float4*)(gB1);
            u32 dstB = smbase + (U_B) * 4;
            for (int i = tid; i < 1536; i += TPB) cp16(dstB + i * 16, srcB + i);
            if (tid < 128) cp16(smbase + (U_A1) * 4 + tid * 16, ((const float4*)gA1) + tid);
            CP_COMMIT();
        }
        for (int it = 0; it < 7; it++) {
            const int buf = it & 1;
            CP_WAIT0();
            __syncthreads();
            if (it + 1 < 7) {
                int base = 2 * (it + 1);
                int npan_n = (base + 1 < KP1) ? 2 : 1;
                const float4* srcB = (const float4*)(gB1 + (size_t)base * B1_PANEL);
                u32 dstB = smbase + (U_B + (buf ^ 1) * 2 * B1_PANEL) * 4;
                int n4 = npan_n * (B1_PANEL / 4);
                for (int i = tid; i < n4; i += TPB) cp16(dstB + i * 16, srcB + i);
                const float4* srcA = (const float4*)(gA1 + (size_t)base * A1_PANEL);
                int na = npan_n * (A1_PANEL / 4);
                if (tid < na)
                    cp16(smbase + (U_A1 + (buf ^ 1) * 2 * A1_PANEL) * 4 + tid * 16, srcA + tid);
                CP_COMMIT();
            }
            int npan = (2 * it + 1 < KP1) ? 2 : 1;
            for (int sub = 0; sub < npan; sub++) {
                const u32* bA = smu + U_A1 + buf * 2 * A1_PANEL + sub * A1_PANEL;
                const u32* bB = smu + U_B + buf * 2 * B1_PANEL + sub * B1_PANEL;
                u32 ah[2][4];
                #pragma unroll
                for (int mt = 0; mt < 2; mt++) {
                    uint4 h = *(const uint4*)&bA[(mt * 32 + lane) * 4];
                    ah[mt][0] = h.x; ah[mt][1] = h.y; ah[mt][2] = h.z; ah[mt][3] = h.w;
                }
                #pragma unroll
                for (int np = 0; np < 3; np++) {
                    int pairIdx = wid * 3 + np;
                    uint4 b4 = *(const uint4*)&bB[(pairIdx * 32 + lane) * 4];
                    #pragma unroll
                    for (int mt = 0; mt < 2; mt++) mma16(acc1[mt][2 * np],     ah[mt], b4.x, b4.y);
                    #pragma unroll
                    for (int mt = 0; mt < 2; mt++) mma16(acc1[mt][2 * np + 1], ah[mt], b4.z, b4.w);
                }
            }
        }

        // ---------------- softmax ----------------
        #pragma unroll
        for (int mt = 0; mt < 2; mt++)
            #pragma unroll
            for (int h = 0; h < 2; h++) {
                float mx = -INFINITY;
                #pragma unroll
                for (int nt = 0; nt < 6; nt++)
                    mx = fmaxf(mx, fmaxf(acc1[mt][nt][2 * h], acc1[mt][nt][2 * h + 1]));
                mx = fmaxf(mx, __shfl_xor_sync(0xffffffffu, mx, 1));
                mx = fmaxf(mx, __shfl_xor_sync(0xffffffffu, mx, 2));
                int row = mt * 16 + gr + 8 * h;
                if (gc == 0) smf[U_PMAX + row * 8 + wid] = mx;
            }
        __syncthreads();
        #pragma unroll
        for (int mt = 0; mt < 2; mt++)
            #pragma unroll
            for (int h = 0; h < 2; h++) {
                int row = mt * 16 + gr + 8 * h;
                float gmax = -INFINITY;
                #pragma unroll
                for (int w = 0; w < 8; w++)
                    gmax = fmaxf(gmax, smf[U_PMAX + row * 8 + w]);
                float s2 = 0.f;
                #pragma unroll
                for (int nt = 0; nt < 6; nt++) {
                    float v0 = __expf(acc1[mt][nt][2 * h] - gmax);
                    float v1 = __expf(acc1[mt][nt][2 * h + 1] - gmax);
                    acc1[mt][nt][2 * h] = v0;
                    acc1[mt][nt][2 * h + 1] = v1;
                    s2 += v0 + v1;
                }
                s2 += __shfl_xor_sync(0xffffffffu, s2, 1);
                s2 += __shfl_xor_sync(0xffffffffu, s2, 2);
                if (gc == 0) smf[U_PSUM + row * 8 + wid] = s2;
            }
        __syncthreads();   // PSUM ready; also GEMM1 staging fully dead -> A2 alias safe
        if (wid == 0 && gc == 0) {
            #pragma unroll
            for (int mt = 0; mt < 2; mt++)
                #pragma unroll
                for (int h = 0; h < 2; h++) {
                    int row = mt * 16 + gr + 8 * h;
                    float tot = 0.f;
                    #pragma unroll
                    for (int w = 0; w < 8; w++) tot += smf[U_PSUM + row * 8 + w];
                    smf[U_RINV + row] = 1.0f / tot;
                }
        }

        // pack Pexp (fp16) into GEMM2 A-fragment layout (aliased at U_A2 = U_B)
        #pragma unroll
        for (int mt = 0; mt < 2; mt++) {
            #pragma unroll
            for (int np = 0; np < 3; np++) {
                int p = wid * 3 + np;
                u32 vh0 = hpack(acc1[mt][2 * np][0], acc1[mt][2 * np][1]);
                u32 vh1 = hpack(acc1[mt][2 * np][2], acc1[mt][2 * np][3]);
                u32 vh2 = hpack(acc1[mt][2 * np + 1][0], acc1[mt][2 * np + 1][1]);
                u32 vh3 = hpack(acc1[mt][2 * np + 1][2], acc1[mt][2 * np + 1][3]);
                *(uint4*)&smu[U_A2 + ((p * 2 + mt) * 32 + lane) * 4] =
                    make_uint4(vh0, vh1, vh2, vh3);
            }
        }
        __syncthreads();

        // ---------------- GEMM2: 12 iterations of 2 panels ----------------
        float acc2[2][4][4];
        #pragma unroll
        for (int mt = 0; mt < 2; mt++)
            #pragma unroll
            for (int nt = 0; nt < 4; nt++)
                #pragma unroll
                for (int e = 0; e < 4; e++) acc2[mt][nt][e] = 0.f;

        {
            const float4* srcB = (const float4*)(gB2);
            u32 dstB = smbase + (U_B2S) * 4;
            for (int i = tid; i < 800; i += TPB) cp16(dstB + i * 16, srcB + i);
            CP_COMMIT();
        }
        for (int it = 0; it < 12; it++) {
            const int buf = it & 1;
            CP_WAIT0();
            __syncthreads();
            if (it + 1 < 12) {
                const float4* srcB = (const float4*)(gB2 + (size_t)(2 * it + 2) * B2_PANEL);
                u32 dstB = smbase + (U_B2S + (buf ^ 1) * 2 * B2_PANEL) * 4;
                for (int i = tid; i < 800; i += TPB) cp16(dstB + i * 16, srcB + i);
                CP_COMMIT();
            }
            #pragma unroll
            for (int sub = 0; sub < 2; sub++) {
                int p = 2 * it + sub;
                const u32* bB = smu + U_B2S + buf * 2 * B2_PANEL + sub * B2_PANEL;
                u32 ah[2][4];
                #pragma unroll
                for (int mt = 0; mt < 2; mt++) {
                    uint4 h = *(const uint4*)&smu[U_A2 + ((p * 2 + mt) * 32 + lane) * 4];
                    ah[mt][0] = h.x; ah[mt][1] = h.y; ah[mt][2] = h.z; ah[mt][3] = h.w;
                }
                for (int nt = 0; nt < ng2; nt++) {
                    int G = g2base + nt;
                    uint2 b2 = *(const uint2*)&bB[(G * 32 + lane) * 2];
                    #pragma unroll
                    for (int mt = 0; mt < 2; mt++) mma16(acc2[mt][nt], ah[mt], b2.x, b2.y);
                }
            }
        }
        __syncthreads();

        // ---------------- epilogue ----------------
        for (int nt = 0; nt < ng2; nt++) {
            int G = g2base + nt;
            int ta = G * 8 + 2 * gc;
            int tb = ta + 1;
            float pn_a = 0.f, pq_a = 0.f, pn_b = 0.f, pq_b = 0.f;
            #pragma unroll
            for (int mt = 0; mt < 2; mt++) {
                int rb1 = mt * 16 + gr;
                int rb2 = rb1 + 8;
                float r1 = smf[U_RINV + rb1];
                float r2 = smf[U_RINV + rb2];
                float v0 = acc2[mt][nt][0] * r1;
                float v1 = acc2[mt][nt][1] * r1;
                float v2 = acc2[mt][nt][2] * r2;
                float v3 = acc2[mt][nt][3] * r2;
                int gd1 = d0 + rb1, gd2 = d0 + rb2;
                float fa1 = 0.f, fa2 = 0.f, fb1 = 0.f, fb2 = 0.f;
                if (ta < T_) { fa1 = Fs[(size_t)ta * C_ + gd1]; fa2 = Fs[(size_t)ta * C_ + gd2]; }
                if (tb < T_) { fb1 = Fs[(size_t)tb * C_ + gd1]; fb2 = Fs[(size_t)tb * C_ + gd2]; }
                pn_a += v0 * fa1 + v2 * fa2;
                pq_a += v0 * v0 + v2 * v2;
                pn_b += v1 * fb1 + v3 * fb2;
                pq_b += v1 * v1 + v3 * v3;
            }
            #pragma unroll
            for (int o = 4; o <= 16; o <<= 1) {
                pn_a += __shfl_xor_sync(0xffffffffu, pn_a, o);
                pq_a += __shfl_xor_sync(0xffffffffu, pq_a, o);
                pn_b += __shfl_xor_sync(0xffffffffu, pn_b, o);
                pq_b += __shfl_xor_sync(0xffffffffu, pq_b, o);
            }
            if (lane < 4) {
                smf[U_PN + ta] += pn_a;
                smf[U_PQ + ta] += pq_a;
                smf[U_PN + tb] += pn_b;
                smf[U_PQ + tb] += pq_b;
            }
        }
        __syncthreads();
    }

    if (tid < NT2) {
        g_pn[(size_t)cid * NT2 + tid] = smf[U_PN + tid];
        g_pq[(size_t)cid * NT2 + tid] = smf[U_PQ + tid];
    }
}

// ==================== merged final kernel ====================

__global__ void final_kernel(const float* __restrict__ xq,
                             const float* __restrict__ xs,
                             float* __restrict__ out) {
    int gw = (blockIdx.x * blockDim.x + threadIdx.x) >> 5;
    int lane = threadIdx.x & 31;
    if (gw < B_ * Q_) {
        int bb = gw / Q_;
        float acc = 0.f;
        for (int n = 0; n < N_; n++) {
            int w = gw * N_ + n;
            int bn = bb * N_ + n;
            float local = -INFINITY;
            for (int t = lane; t < T_; t += 32) {
                float num = g_pn[(size_t)(2 * w) * NT2 + t] + g_pn[(size_t)(2 * w + 1) * NT2 + t];
                float nrm = g_pq[(size_t)(2 * w) * NT2 + t] + g_pq[(size_t)(2 * w + 1) * NT2 + t];
                float denom = fmaxf(sqrtf(nrm) * g_nfs[bn * T_ + t], 1e-8f);
                local = fmaxf(local, num / denom);
            }
            #pragma unroll
            for (int o = 16; o > 0; o >>= 1)
                local = fmaxf(local, __shfl_xor_sync(0xffffffffu, local, o));
            acc += local;
        }
        if (lane == 0) out[gw] = acc * (1.0f / N_);
    } else if (gw < B_ * Q_ + B_ * Q_ * N_) {
        int w = gw - B_ * Q_;
        int nn = w % N_;
        int qq = (w / N_) % Q_;
        int bb = w / (N_ * Q_);
        const float* q = xq + (size_t)(bb * Q_ + qq) * D_;
        const float* s = xs + (size_t)(bb * N_ + nn) * D_;
        float dot = 0.f, nq = 0.f, ns = 0.f;
        #pragma unroll
        for (int u = 0; u < D_ / 32; u++) {
            float a = q[lane + 32 * u];
            float b = s[lane + 32 * u];
            dot += a * b;
            nq += a * a;
            ns += b * b;
        }
        #pragma unroll
        for (int o = 16; o > 0; o >>= 1) {
            dot += __shfl_xor_sync(0xffffffffu, dot, o);
            nq  += __shfl_xor_sync(0xffffffffu, nq, o);
            ns  += __shfl_xor_sync(0xffffffffu, ns, o);
        }
        if (lane == 0) {
            float den = fmaxf(sqrtf(nq), 1e-12f) * fmaxf(sqrtf(ns), 1e-12f);
            out[B_ * Q_ + w] = 10.0f * dot / den;
        }
    }
}

extern "C" void kernel_launch(void* const* d_in, const int* in_sizes, int n_in,
                              void* d_out, int out_size) {
    const float* fq = (const float*)d_in[0];
    const float* fs = (const float*)d_in[1];
    const float* xq = (const float*)d_in[2];
    const float* xs = (const float*)d_in[3];
    float* out = (float*)d_out;

    pack_all<<<NB_A1 + NB_B1 + NB_B2 + 70, 256>>>(fq, fs);

    const size_t smem_bytes = (size_t)U_TOT * sizeof(u32);
    cudaFuncSetAttribute(episodic_main,
                         cudaFuncAttributeMaxDynamicSharedMemorySize,
                         (int)smem_bytes);
    episodic_main<<<1500, TPB, smem_bytes>>>(fs);

    final_kernel<<<(900 * 32 + 255) / 256, 256>>>(xq, xs, out);
}